// round 7
// baseline (speedup 1.0000x reference)
#include <cuda_runtime.h>
#include <cstdint>
#include <cstdio>

#define NTOK   343
#define NWIN   256
#define NHEADS 12
#define HDIM   32
#define CDIM   384
#define MROWS  (NWIN * NTOK)     // 87808
#define QKVC   (3 * CDIM)        // 1152
#define NPAD   352               // 343 padded to 11*32
#define KPAD   384               // 343 padded to 6*64

// ---------------- scratch (static device globals; no allocation allowed) ----
__device__ float g_qkv[(size_t)MROWS * QKVC];        // qkv activations
__device__ float g_att[(size_t)MROWS * CDIM];        // attention output (tf32-rounded)
__device__ float g_bias[NHEADS * NPAD * KPAD];       // padded rel-pos bias (+ -1e30 pad keys)
__device__ float g_xr[(size_t)MROWS * CDIM];         // tf32-rounded x
__device__ float g_wqt[(size_t)QKVC * CDIM];         // qkv_w transposed+rounded
__device__ float g_wpt[(size_t)CDIM * CDIM];         // proj_w transposed+rounded

// ======================= helpers ============================================
__device__ __forceinline__ float tf32_rna(float v) {
    uint32_t u;
    asm("cvt.rna.tf32.f32 %0, %1;" : "=r"(u) : "f"(v));
    return __uint_as_float(u);
}
__device__ __forceinline__ uint32_t tf32u(float v) {
    uint32_t u;
    asm("cvt.rna.tf32.f32 %0, %1;" : "=r"(u) : "f"(v));
    return u;
}
#define CP_ASYNC16(dst, src) \
    asm volatile("cp.async.cg.shared.global [%0], [%1], 16;" :: "r"(dst), "l"(src))
#define CP_COMMIT() asm volatile("cp.async.commit_group;" ::: "memory")
#define CP_WAIT1()  asm volatile("cp.async.wait_group 1;" ::: "memory")
#define CP_WAIT0()  asm volatile("cp.async.wait_group 0;" ::: "memory")

__device__ __forceinline__ uint32_t smem_u32(const void* p) {
    uint32_t a;
    asm("{ .reg .u64 t; cvta.to.shared.u64 t, %1; cvt.u32.u64 %0, t; }" : "=r"(a) : "l"(p));
    return a;
}

__device__ __forceinline__ void mma_tf32(float* c, const uint32_t* a, const uint32_t* b) {
    asm volatile(
        "mma.sync.aligned.m16n8k8.row.col.f32.tf32.tf32.f32 "
        "{%0,%1,%2,%3}, {%4,%5,%6,%7}, {%8,%9}, {%0,%1,%2,%3};"
        : "+f"(c[0]), "+f"(c[1]), "+f"(c[2]), "+f"(c[3])
        : "r"(a[0]), "r"(a[1]), "r"(a[2]), "r"(a[3]), "r"(b[0]), "r"(b[1]));
}

// ======================= prep kernels =======================================
__global__ void round_tf32_kernel(const float* __restrict__ in, float* __restrict__ out, int n4) {
    int i = blockIdx.x * blockDim.x + threadIdx.x;
    if (i < n4) {
        float4 v = reinterpret_cast<const float4*>(in)[i];
        v.x = tf32_rna(v.x); v.y = tf32_rna(v.y);
        v.z = tf32_rna(v.z); v.w = tf32_rna(v.w);
        reinterpret_cast<float4*>(out)[i] = v;
    }
}

__global__ void transpose_round_kernel(const float* __restrict__ W, float* __restrict__ Wt,
                                       int K, int Nw) {
    __shared__ float t[32][33];
    int n0 = blockIdx.x * 32, k0 = blockIdx.y * 32;
#pragma unroll
    for (int s = 0; s < 4; ++s) {
        int k = k0 + threadIdx.y + s * 8;
        t[threadIdx.y + s * 8][threadIdx.x] = tf32_rna(W[(size_t)k * Nw + n0 + threadIdx.x]);
    }
    __syncthreads();
#pragma unroll
    for (int s = 0; s < 4; ++s) {
        int n = n0 + threadIdx.y + s * 8;
        Wt[(size_t)n * K + k0 + threadIdx.x] = t[threadIdx.x][threadIdx.y + s * 8];
    }
}

// padded bias: [12][352][384]; pad keys -> -1e30 (softmax zero), pad rows -> 0
__global__ void bias_expand_pad_kernel(const float* __restrict__ bt,
                                       const int* __restrict__ ridx,
                                       float* __restrict__ bf)
{
    int idx = blockIdx.x * blockDim.x + threadIdx.x;
    if (idx < NHEADS * NPAD * KPAD) {
        int h   = idx / (NPAD * KPAD);
        int rem = idx - h * NPAD * KPAD;
        int r   = rem / KPAD;
        int k   = rem - r * KPAD;
        float v;
        if (k >= NTOK)      v = -1e30f;
        else if (r >= NTOK) v = 0.f;
        else                v = bt[ridx[r * NTOK + k] * NHEADS + h];
        bf[idx] = v;
    }
}

// ======================= hybrid TF32 GEMM: HMMA + FFMA pipes ================
// C[M,Ntot] = A[M,384] @ Wt[Ntot,384]^T + bias.
// CTA 128x128. blockIdx.y%32 < 7 (21.9% of m-tiles) -> FFMA path (fma pipe);
// else -> mma.sync path (tensor pipe). Both co-resident per SM (2 CTAs).
#define GK      384
#define GNCHUNK 12
#define LDT     36
#define GSM_TOT (4 * 128 * LDT * 4)    // 73728 B (MMA path; FFMA uses a subset)

__global__ __launch_bounds__(256, 2) void mma_gemm_kernel(
    const float* __restrict__ A, const float* __restrict__ Wt,
    const float* __restrict__ bias, float* __restrict__ C, int Ntot)
{
    extern __shared__ float sm[];
    const int tid = threadIdx.x;
    const int bm = blockIdx.y * 128;
    const int bn = blockIdx.x * 128;

    if ((blockIdx.y & 31) < 7) {
        // ================= FFMA path (fma pipe) ============================
        float (*As)[132] = reinterpret_cast<float(*)[132]>(sm);
        float (*Ws)[132] = reinterpret_cast<float(*)[132]>(sm + 16 * 132);
        const int tx = tid & 15;
        const int ty = tid >> 4;

        float acc[8][8];
#pragma unroll
        for (int i = 0; i < 8; ++i)
#pragma unroll
            for (int j = 0; j < 8; ++j) acc[i][j] = 0.f;

        for (int k0 = 0; k0 < GK; k0 += 16) {
#pragma unroll
            for (int s = 0; s < 2; ++s) {
                int vi = tid + s * 256;          // 512 float4 slots per tile
                int r  = vi >> 2;
                int c4 = (vi & 3) << 2;
                float4 av = *reinterpret_cast<const float4*>(
                    &A[(size_t)(bm + r) * GK + k0 + c4]);
                As[c4 + 0][r] = av.x; As[c4 + 1][r] = av.y;
                As[c4 + 2][r] = av.z; As[c4 + 3][r] = av.w;
                float4 wv = *reinterpret_cast<const float4*>(
                    &Wt[(size_t)(bn + r) * GK + k0 + c4]);
                Ws[c4 + 0][r] = wv.x; Ws[c4 + 1][r] = wv.y;
                Ws[c4 + 2][r] = wv.z; Ws[c4 + 3][r] = wv.w;
            }
            __syncthreads();

#pragma unroll
            for (int kk = 0; kk < 16; ++kk) {
                float4 a0 = *reinterpret_cast<const float4*>(&As[kk][ty * 8]);
                float4 a1 = *reinterpret_cast<const float4*>(&As[kk][ty * 8 + 4]);
                float4 w0 = *reinterpret_cast<const float4*>(&Ws[kk][tx * 8]);
                float4 w1 = *reinterpret_cast<const float4*>(&Ws[kk][tx * 8 + 4]);
                float a[8] = {a0.x, a0.y, a0.z, a0.w, a1.x, a1.y, a1.z, a1.w};
                float w[8] = {w0.x, w0.y, w0.z, w0.w, w1.x, w1.y, w1.z, w1.w};
#pragma unroll
                for (int i = 0; i < 8; ++i)
#pragma unroll
                    for (int j = 0; j < 8; ++j)
                        acc[i][j] += a[i] * w[j];
            }
            __syncthreads();
        }

#pragma unroll
        for (int i = 0; i < 8; ++i) {
            int row = bm + ty * 8 + i;
#pragma unroll
            for (int j4 = 0; j4 < 2; ++j4) {
                int col = bn + tx * 8 + j4 * 4;
                float4 o;
                o.x = acc[i][j4 * 4 + 0] + __ldg(&bias[col + 0]);
                o.y = acc[i][j4 * 4 + 1] + __ldg(&bias[col + 1]);
                o.z = acc[i][j4 * 4 + 2] + __ldg(&bias[col + 2]);
                o.w = acc[i][j4 * 4 + 3] + __ldg(&bias[col + 3]);
                *reinterpret_cast<float4*>(&C[(size_t)row * Ntot + col]) = o;
            }
        }
        return;
    }

    // ================= MMA path (tensor pipe, R5 config) ===================
    float* sA[2] = { sm,               sm + 128 * LDT };
    float* sB[2] = { sm + 2*128*LDT,   sm + 3*128*LDT };
    const uint32_t sAu[2] = { smem_u32(sA[0]), smem_u32(sA[1]) };
    const uint32_t sBu[2] = { smem_u32(sB[0]), smem_u32(sB[1]) };

    const int wid = tid >> 5, lid = tid & 31;
    const int g = lid >> 2, t4 = lid & 3;
    const int wm = (wid & 1) * 64;
    const int wn = (wid >> 1) * 32;

    float acc[4][4][4];
#pragma unroll
    for (int i = 0; i < 4; ++i)
#pragma unroll
        for (int j = 0; j < 4; ++j)
#pragma unroll
            for (int q = 0; q < 4; ++q) acc[i][j][q] = 0.f;

    auto load_chunk = [&](int c, int buf) {
        const float* ap = A  + (size_t)bm * GK + c * 32;
        const float* bp = Wt + (size_t)bn * GK + c * 32;
#pragma unroll
        for (int i = 0; i < 4; ++i) {
            int f = tid + i * 256;
            int row = f >> 3, c4 = (f & 7) * 4;
            CP_ASYNC16(sAu[buf] + (uint32_t)(row * LDT + c4) * 4,
                       ap + (size_t)row * GK + c4);
        }
#pragma unroll
        for (int i = 0; i < 4; ++i) {
            int f = tid + i * 256;
            int row = f >> 3, c4 = (f & 7) * 4;
            CP_ASYNC16(sBu[buf] + (uint32_t)(row * LDT + c4) * 4,
                       bp + (size_t)row * GK + c4);
        }
    };

    load_chunk(0, 0);
    CP_COMMIT();

    for (int c = 0; c < GNCHUNK; ++c) {
        const int b = c & 1;
        if (c + 1 < GNCHUNK) {
            load_chunk(c + 1, b ^ 1);
            CP_COMMIT();
            CP_WAIT1();
        } else {
            CP_WAIT0();
        }
        __syncthreads();

        const float* As = sA[b];
        const float* Bs = sB[b];
#pragma unroll
        for (int ks = 0; ks < 4; ++ks) {
            const int k = ks * 8 + t4;
            uint32_t af[4][4], bf[4][2];
#pragma unroll
            for (int mi = 0; mi < 4; ++mi) {
                const int r = wm + mi * 16 + g;
                af[mi][0] = __float_as_uint(As[r * LDT + k]);
                af[mi][1] = __float_as_uint(As[(r + 8) * LDT + k]);
                af[mi][2] = __float_as_uint(As[r * LDT + k + 4]);
                af[mi][3] = __float_as_uint(As[(r + 8) * LDT + k + 4]);
            }
#pragma unroll
            for (int ni = 0; ni < 4; ++ni) {
                const int n = wn + ni * 8 + g;
                bf[ni][0] = __float_as_uint(Bs[n * LDT + k]);
                bf[ni][1] = __float_as_uint(Bs[n * LDT + k + 4]);
            }
#pragma unroll
            for (int mi = 0; mi < 4; ++mi)
#pragma unroll
                for (int ni = 0; ni < 4; ++ni)
                    mma_tf32(acc[mi][ni], af[mi], bf[ni]);
        }
        __syncthreads();
    }

#pragma unroll
    for (int mi = 0; mi < 4; ++mi) {
#pragma unroll
        for (int ni = 0; ni < 4; ++ni) {
            const int row = bm + wm + mi * 16 + g;
            const int col = bn + wn + ni * 8 + t4 * 2;
            const float b0 = __ldg(&bias[col]), b1 = __ldg(&bias[col + 1]);
            float2 v0 = { acc[mi][ni][0] + b0, acc[mi][ni][1] + b1 };
            float2 v1 = { acc[mi][ni][2] + b0, acc[mi][ni][3] + b1 };
            *reinterpret_cast<float2*>(&C[(size_t)row * Ntot + col]) = v0;
            *reinterpret_cast<float2*>(&C[(size_t)(row + 8) * Ntot + col]) = v1;
        }
    }
}

// ======================= tensor-core flash attention (unchanged) ============
#define AT_THREADS 352
#define LDKV 40     // K/V smem stride: conflict-free b-frag loads
#define LDP  36     // per-warp P/Q smem stride: conflict-free a-frag loads
#define AT_SMEM ((2 * 64 * LDKV + 11 * 32 * LDP) * 4)   // 71168 B

__global__ __launch_bounds__(AT_THREADS, 1) void attn_mma_kernel(
    const float* __restrict__ qkv, const float* __restrict__ biasP,
    float* __restrict__ out)
{
    extern __shared__ float sm[];
    float* Ks = sm;                 // [64][LDKV]
    float* Vs = sm + 64 * LDKV;     // [64][LDKV]
    const int h   = blockIdx.x;
    const int b   = blockIdx.y;
    const int tid = threadIdx.x;
    const int wid = tid >> 5, lid = tid & 31;
    const int g = lid >> 2, t4 = lid & 3;
    float* Pw = sm + 2 * 64 * LDKV + wid * (32 * LDP);   // warp-private
    const int wm = wid * 32;
    const float* base = qkv + (size_t)b * NTOK * QKVC;
    const float scale = 0.17677669529663687f;

#pragma unroll
    for (int i = 0; i < 8; ++i) {
        int f = lid + i * 32;
        int row = f >> 3, c4 = (f & 7) * 4;
        int qrow = wm + row;
        float4 v = make_float4(0.f, 0.f, 0.f, 0.f);
        if (qrow < NTOK)
            v = *reinterpret_cast<const float4*>(base + (size_t)qrow * QKVC + h * HDIM + c4);
        Pw[row * LDP + c4 + 0] = v.x;
        Pw[row * LDP + c4 + 1] = v.y;
        Pw[row * LDP + c4 + 2] = v.z;
        Pw[row * LDP + c4 + 3] = v.w;
    }
    __syncwarp();

    uint32_t qa[2][4][4];
#pragma unroll
    for (int mi = 0; mi < 2; ++mi)
#pragma unroll
        for (int ks = 0; ks < 4; ++ks) {
            const int r0 = (mi * 16 + g) * LDP, r1 = (mi * 16 + 8 + g) * LDP;
            const int k = ks * 8 + t4;
            qa[mi][ks][0] = tf32u(Pw[r0 + k] * scale);
            qa[mi][ks][1] = tf32u(Pw[r1 + k] * scale);
            qa[mi][ks][2] = tf32u(Pw[r0 + k + 4] * scale);
            qa[mi][ks][3] = tf32u(Pw[r1 + k + 4] * scale);
        }

    float o[2][4][4];
#pragma unroll
    for (int mi = 0; mi < 2; ++mi)
#pragma unroll
        for (int n = 0; n < 4; ++n)
#pragma unroll
            for (int q = 0; q < 4; ++q) o[mi][n][q] = 0.f;
    float mrow[2][2] = {{-1e30f, -1e30f}, {-1e30f, -1e30f}};
    float lrow[2][2] = {{0.f, 0.f}, {0.f, 0.f}};

    const float* bp = biasP + ((size_t)h * NPAD + wm) * KPAD;

    for (int ch = 0; ch < 6; ++ch) {
        const int j0 = ch * 64;
        __syncthreads();
#pragma unroll
        for (int i = 0; i < 2; ++i) {
            int f = tid + i * AT_THREADS;
            if (f < 512) {
                int row = f >> 3, c4 = (f & 7) * 4;
                int kr = j0 + row;
                float4 kv = make_float4(0.f, 0.f, 0.f, 0.f);
                float4 vv = make_float4(0.f, 0.f, 0.f, 0.f);
                if (kr < NTOK) {
                    const float* rp = base + (size_t)kr * QKVC + h * HDIM;
                    kv = *reinterpret_cast<const float4*>(rp + CDIM + c4);
                    vv = *reinterpret_cast<const float4*>(rp + 2 * CDIM + c4);
                }
                float4 kr4 = { tf32_rna(kv.x), tf32_rna(kv.y), tf32_rna(kv.z), tf32_rna(kv.w) };
                float4 vr4 = { tf32_rna(vv.x), tf32_rna(vv.y), tf32_rna(vv.z), tf32_rna(vv.w) };
                *reinterpret_cast<float4*>(&Ks[row * LDKV + c4]) = kr4;
                *reinterpret_cast<float4*>(&Vs[row * LDKV + c4]) = vr4;
            }
        }
        __syncthreads();

        float c[2][8][4];
#pragma unroll
        for (int mi = 0; mi < 2; ++mi) {
            const float* b0p = bp + (size_t)(mi * 16 + g) * KPAD + j0 + 2 * t4;
            const float* b1p = bp + (size_t)(mi * 16 + 8 + g) * KPAD + j0 + 2 * t4;
#pragma unroll
            for (int ni = 0; ni < 8; ++ni) {
                float2 v0 = *reinterpret_cast<const float2*>(b0p + ni * 8);
                float2 v1 = *reinterpret_cast<const float2*>(b1p + ni * 8);
                c[mi][ni][0] = v0.x; c[mi][ni][1] = v0.y;
                c[mi][ni][2] = v1.x; c[mi][ni][3] = v1.y;
            }
        }
#pragma unroll
        for (int ks = 0; ks < 4; ++ks) {
            const int k = ks * 8 + t4;
            uint32_t kb[8][2];
#pragma unroll
            for (int ni = 0; ni < 8; ++ni) {
                kb[ni][0] = __float_as_uint(Ks[(ni * 8 + g) * LDKV + k]);
                kb[ni][1] = __float_as_uint(Ks[(ni * 8 + g) * LDKV + k + 4]);
            }
#pragma unroll
            for (int mi = 0; mi < 2; ++mi)
#pragma unroll
                for (int ni = 0; ni < 8; ++ni)
                    mma_tf32(c[mi][ni], qa[mi][ks], kb[ni]);
        }

#pragma unroll
        for (int mi = 0; mi < 2; ++mi) {
            float mx0 = c[mi][0][0], mx1 = c[mi][0][2];
#pragma unroll
            for (int ni = 0; ni < 8; ++ni) {
                mx0 = fmaxf(mx0, fmaxf(c[mi][ni][0], c[mi][ni][1]));
                mx1 = fmaxf(mx1, fmaxf(c[mi][ni][2], c[mi][ni][3]));
            }
            mx0 = fmaxf(mx0, __shfl_xor_sync(0xFFFFFFFF, mx0, 1));
            mx0 = fmaxf(mx0, __shfl_xor_sync(0xFFFFFFFF, mx0, 2));
            mx1 = fmaxf(mx1, __shfl_xor_sync(0xFFFFFFFF, mx1, 1));
            mx1 = fmaxf(mx1, __shfl_xor_sync(0xFFFFFFFF, mx1, 2));
            float nm0 = fmaxf(mrow[mi][0], mx0);
            float nm1 = fmaxf(mrow[mi][1], mx1);
            float cr0 = __expf(mrow[mi][0] - nm0);
            float cr1 = __expf(mrow[mi][1] - nm1);
            mrow[mi][0] = nm0; mrow[mi][1] = nm1;
#pragma unroll
            for (int n = 0; n < 4; ++n) {
                o[mi][n][0] *= cr0; o[mi][n][1] *= cr0;
                o[mi][n][2] *= cr1; o[mi][n][3] *= cr1;
            }
            float s0 = 0.f, s1 = 0.f;
#pragma unroll
            for (int ni = 0; ni < 8; ++ni) {
                c[mi][ni][0] = __expf(c[mi][ni][0] - nm0); s0 += c[mi][ni][0];
                c[mi][ni][1] = __expf(c[mi][ni][1] - nm0); s0 += c[mi][ni][1];
                c[mi][ni][2] = __expf(c[mi][ni][2] - nm1); s1 += c[mi][ni][2];
                c[mi][ni][3] = __expf(c[mi][ni][3] - nm1); s1 += c[mi][ni][3];
            }
            s0 += __shfl_xor_sync(0xFFFFFFFF, s0, 1);
            s0 += __shfl_xor_sync(0xFFFFFFFF, s0, 2);
            s1 += __shfl_xor_sync(0xFFFFFFFF, s1, 1);
            s1 += __shfl_xor_sync(0xFFFFFFFF, s1, 2);
            lrow[mi][0] = lrow[mi][0] * cr0 + s0;
            lrow[mi][1] = lrow[mi][1] * cr1 + s1;
        }

#pragma unroll
        for (int grp = 0; grp < 4; ++grp) {
#pragma unroll
            for (int mi = 0; mi < 2; ++mi)
#pragma unroll
                for (int q = 0; q < 2; ++q) {
                    const int nt = 2 * grp + q;
                    float2 p0 = { tf32_rna(c[mi][nt][0]), tf32_rna(c[mi][nt][1]) };
                    float2 p1 = { tf32_rna(c[mi][nt][2]), tf32_rna(c[mi][nt][3]) };
                    *reinterpret_cast<float2*>(&Pw[(mi * 16 + g) * LDP + q * 8 + 2 * t4]) = p0;
                    *reinterpret_cast<float2*>(&Pw[(mi * 16 + 8 + g) * LDP + q * 8 + 2 * t4]) = p1;
                }
            __syncwarp();
#pragma unroll
            for (int ks2 = 0; ks2 < 2; ++ks2) {
                uint32_t pa[2][4];
#pragma unroll
                for (int mi = 0; mi < 2; ++mi) {
                    const int r0 = (mi * 16 + g) * LDP, r1 = (mi * 16 + 8 + g) * LDP;
                    const int k = ks2 * 8 + t4;
                    pa[mi][0] = __float_as_uint(Pw[r0 + k]);
                    pa[mi][1] = __float_as_uint(Pw[r1 + k]);
                    pa[mi][2] = __float_as_uint(Pw[r0 + k + 4]);
                    pa[mi][3] = __float_as_uint(Pw[r1 + k + 4]);
                }
                uint32_t vb[4][2];
                const int kr = grp * 16 + ks2 * 8;
#pragma unroll
                for (int n = 0; n < 4; ++n) {
                    vb[n][0] = __float_as_uint(Vs[(kr + t4) * LDKV + n * 8 + g]);
                    vb[n][1] = __float_as_uint(Vs[(kr + t4 + 4) * LDKV + n * 8 + g]);
                }
#pragma unroll
                for (int mi = 0; mi < 2; ++mi)
#pragma unroll
                    for (int n = 0; n < 4; ++n)
                        mma_tf32(o[mi][n], pa[mi], vb[n]);
            }
            __syncwarp();
        }
    }

#pragma unroll
    for (int mi = 0; mi < 2; ++mi) {
        const float i0 = 1.f / lrow[mi][0];
        const float i1 = 1.f / lrow[mi][1];
        const int r0 = wm + mi * 16 + g;
        const int r1 = r0 + 8;
        if (r0 < NTOK) {
            float* op = out + ((size_t)b * NTOK + r0) * CDIM + h * HDIM + 2 * t4;
#pragma unroll
            for (int n = 0; n < 4; ++n) {
                float2 v = { tf32_rna(o[mi][n][0] * i0), tf32_rna(o[mi][n][1] * i0) };
                *reinterpret_cast<float2*>(op + n * 8) = v;
            }
        }
        if (r1 < NTOK) {
            float* op = out + ((size_t)b * NTOK + r1) * CDIM + h * HDIM + 2 * t4;
#pragma unroll
            for (int n = 0; n < 4; ++n) {
                float2 v = { tf32_rna(o[mi][n][2] * i1), tf32_rna(o[mi][n][3] * i1) };
                *reinterpret_cast<float2*>(op + n * 8) = v;
            }
        }
    }
}

// ---------------- launch ------------------------------------------------------
extern "C" void kernel_launch(void* const* d_in, const int* in_sizes, int n_in,
                              void* d_out, int out_size)
{
    const float* x       = (const float*)d_in[0];
    const float* qkv_w   = (const float*)d_in[1];
    const float* qkv_b   = (const float*)d_in[2];
    const float* proj_w  = (const float*)d_in[3];
    const float* proj_b  = (const float*)d_in[4];
    const float* bt      = (const float*)d_in[5];
    const int*   ridx    = (const int*)d_in[6];
    float*       out     = (float*)d_out;

    void *p_qkv, *p_att, *p_bias, *p_xr, *p_wqt, *p_wpt;
    cudaGetSymbolAddress(&p_qkv,  g_qkv);
    cudaGetSymbolAddress(&p_att,  g_att);
    cudaGetSymbolAddress(&p_bias, g_bias);
    cudaGetSymbolAddress(&p_xr,   g_xr);
    cudaGetSymbolAddress(&p_wqt,  g_wqt);
    cudaGetSymbolAddress(&p_wpt,  g_wpt);
    float* qkv  = (float*)p_qkv;
    float* att  = (float*)p_att;
    float* bias = (float*)p_bias;
    float* xr   = (float*)p_xr;
    float* wqt  = (float*)p_wqt;
    float* wpt  = (float*)p_wpt;

    cudaFuncSetAttribute(mma_gemm_kernel,
                         cudaFuncAttributeMaxDynamicSharedMemorySize, GSM_TOT);
    cudaFuncSetAttribute(attn_mma_kernel,
                         cudaFuncAttributeMaxDynamicSharedMemorySize, AT_SMEM);

    // 0) prep: tf32-round x; transpose+round weights; expand padded bias
    {
        int n4 = MROWS * CDIM / 4;
        round_tf32_kernel<<<(n4 + 255) / 256, 256>>>(x, xr, n4);
        transpose_round_kernel<<<dim3(QKVC / 32, CDIM / 32), dim3(32, 8)>>>(qkv_w, wqt, CDIM, QKVC);
        transpose_round_kernel<<<dim3(CDIM / 32, CDIM / 32), dim3(32, 8)>>>(proj_w, wpt, CDIM, CDIM);
        int total = NHEADS * NPAD * KPAD;
        bias_expand_pad_kernel<<<(total + 255) / 256, 256>>>(bt, ridx, bias);
    }

    // 1) QKV projection (hybrid HMMA+FFMA)
    mma_gemm_kernel<<<dim3(QKVC / 128, MROWS / 128), 256, GSM_TOT>>>(xr, wqt, qkv_b, qkv, QKVC);

    // 2) tensor-core flash attention
    attn_mma_kernel<<<dim3(NHEADS, NWIN), AT_THREADS, AT_SMEM>>>(qkv, bias, att);

    // 3) output projection (hybrid HMMA+FFMA)
    mma_gemm_kernel<<<dim3(CDIM / 128, MROWS / 128), 256, GSM_TOT>>>(att, wpt, proj_b, out, CDIM);
}

// round 8
// speedup vs baseline: 1.9586x; 1.9586x over previous
#include <cuda_runtime.h>
#include <cuda_fp16.h>
#include <cstdint>
#include <cstdio>

#define NTOK   343
#define NWIN   256
#define NHEADS 12
#define HDIM   32
#define CDIM   384
#define MROWS  (NWIN * NTOK)     // 87808
#define QKVC   (3 * CDIM)        // 1152
#define NPAD   384               // query rows padded to 3*128
#define KPAD   384               // keys padded to 6*64

// ---------------- scratch (static device globals) ---------------------------
__device__ __half g_qkv[(size_t)MROWS * QKVC];     // qkv activations (half)
__device__ __half g_att[(size_t)MROWS * CDIM];     // attention output (half)
__device__ __half g_biasH[NHEADS * NPAD * KPAD];   // padded rel-pos bias (half)
__device__ __half g_xh[(size_t)MROWS * CDIM];      // x -> half
__device__ __half g_wqt[(size_t)QKVC * CDIM];      // qkv_w^T half
__device__ __half g_wpt[(size_t)CDIM * CDIM];      // proj_w^T half

// ======================= helpers ============================================
__device__ __forceinline__ uint32_t smem_u32(const void* p) {
    uint32_t a;
    asm("{ .reg .u64 t; cvta.to.shared.u64 t, %1; cvt.u32.u64 %0, t; }" : "=r"(a) : "l"(p));
    return a;
}
// pack {lo, hi} floats into f16x2 register
__device__ __forceinline__ uint32_t pack_h2(float lo, float hi) {
    uint32_t r;
    asm("cvt.rn.f16x2.f32 %0, %1, %2;" : "=r"(r) : "f"(hi), "f"(lo));
    return r;
}
#define CP_ASYNC16(dst, src) \
    asm volatile("cp.async.cg.shared.global [%0], [%1], 16;" :: "r"(dst), "l"(src))
#define CP_ASYNC16P(dst, src, n) \
    asm volatile("cp.async.cg.shared.global [%0], [%1], 16, %2;" :: "r"(dst), "l"(src), "r"(n))
#define CP_COMMIT() asm volatile("cp.async.commit_group;" ::: "memory")
#define CP_WAIT1()  asm volatile("cp.async.wait_group 1;" ::: "memory")
#define CP_WAIT0()  asm volatile("cp.async.wait_group 0;" ::: "memory")

__device__ __forceinline__ void mma_f16(float* c, const uint32_t* a, const uint32_t* b) {
    asm volatile(
        "mma.sync.aligned.m16n8k16.row.col.f32.f16.f16.f32 "
        "{%0,%1,%2,%3}, {%4,%5,%6,%7}, {%8,%9}, {%0,%1,%2,%3};"
        : "+f"(c[0]), "+f"(c[1]), "+f"(c[2]), "+f"(c[3])
        : "r"(a[0]), "r"(a[1]), "r"(a[2]), "r"(a[3]), "r"(b[0]), "r"(b[1]));
}

// ======================= prep kernels =======================================
__global__ void f32_to_h_kernel(const float* __restrict__ in, __half* __restrict__ out, int n4) {
    int i = blockIdx.x * blockDim.x + threadIdx.x;
    if (i < n4) {
        float4 v = reinterpret_cast<const float4*>(in)[i];
        uint2 o;
        o.x = pack_h2(v.x, v.y);
        o.y = pack_h2(v.z, v.w);
        reinterpret_cast<uint2*>(out)[i] = o;
    }
}

// W[K][Nw] fp32 -> Wt[Nw][K] half
__global__ void transpose_h_kernel(const float* __restrict__ W, __half* __restrict__ Wt,
                                   int K, int Nw) {
    __shared__ float t[32][33];
    int n0 = blockIdx.x * 32, k0 = blockIdx.y * 32;
#pragma unroll
    for (int s = 0; s < 4; ++s) {
        int k = k0 + threadIdx.y + s * 8;
        t[threadIdx.y + s * 8][threadIdx.x] = W[(size_t)k * Nw + n0 + threadIdx.x];
    }
    __syncthreads();
#pragma unroll
    for (int s = 0; s < 4; ++s) {
        int n = n0 + threadIdx.y + s * 8;
        Wt[(size_t)n * K + k0 + threadIdx.x] = __float2half(t[threadIdx.x][threadIdx.y + s * 8]);
    }
}

// padded bias half: [12][384][384]; pad keys -> -60000 (softmax zero)
__global__ void bias_expand_h_kernel(const float* __restrict__ bt,
                                     const int* __restrict__ ridx,
                                     __half* __restrict__ bf)
{
    int idx = blockIdx.x * blockDim.x + threadIdx.x;
    if (idx < NHEADS * NPAD * KPAD) {
        int h   = idx / (NPAD * KPAD);
        int rem = idx - h * NPAD * KPAD;
        int r   = rem / KPAD;
        int k   = rem - r * KPAD;
        float v;
        if (k >= NTOK)      v = -60000.f;
        else if (r >= NTOK) v = 0.f;
        else                v = bt[ridx[r * NTOK + k] * NHEADS + h];
        bf[idx] = __float2half(v);
    }
}

// ======================= fp16 mma GEMM ======================================
// C[M,Ntot] = A[M,384] @ Wt[Ntot,384]^T + bias (fp32 accum).
// CTA 128x128, BK=64 halves, 256 threads (8 warps 2m x 4n?? -> 2m x 4n as R5:
// wm=(wid&1)*64, wn=(wid>>1)*32), m16n8k16.
#define GK       384
#define GNCHUNK  6
#define LDTH     72                      // halves per smem row (64 + 8 pad)
#define GTILE_H  (128 * LDTH)            // halves per tile buffer
#define GSM_TOT  (4 * GTILE_H * 2)       // bytes = 73728

template<bool OUT_FLOAT>
__global__ __launch_bounds__(256, 2) void mma_gemm_h(
    const __half* __restrict__ A, const __half* __restrict__ Wt,
    const float* __restrict__ bias, void* __restrict__ Cout, int Ntot)
{
    extern __shared__ __half smh[];
    __half* sA[2] = { smh,               smh + GTILE_H };
    __half* sB[2] = { smh + 2 * GTILE_H, smh + 3 * GTILE_H };
    const uint32_t sAu[2] = { smem_u32(sA[0]), smem_u32(sA[1]) };
    const uint32_t sBu[2] = { smem_u32(sB[0]), smem_u32(sB[1]) };

    const int tid = threadIdx.x;
    const int wid = tid >> 5, lid = tid & 31;
    const int g = lid >> 2, t4 = lid & 3;
    const int wm = (wid & 1) * 64;
    const int wn = (wid >> 1) * 32;
    const int bm = blockIdx.y * 128;
    const int bn = blockIdx.x * 128;

    float acc[4][4][4];
#pragma unroll
    for (int i = 0; i < 4; ++i)
#pragma unroll
        for (int j = 0; j < 4; ++j)
#pragma unroll
            for (int q = 0; q < 4; ++q) acc[i][j][q] = 0.f;

    // chunk c covers halves [c*64, c*64+64)
    auto load_chunk = [&](int c, int buf) {
        const __half* ap = A  + (size_t)bm * GK + c * 64;
        const __half* bp = Wt + (size_t)bn * GK + c * 64;
#pragma unroll
        for (int i = 0; i < 4; ++i) {                 // A: 128 rows x 8 slots
            int f = tid + i * 256;
            int row = f >> 3, c16 = (f & 7) * 8;      // 8 halves per 16B
            CP_ASYNC16(sAu[buf] + (uint32_t)(row * LDTH + c16) * 2,
                       ap + (size_t)row * GK + c16);
        }
#pragma unroll
        for (int i = 0; i < 4; ++i) {                 // B: 128 rows x 8 slots
            int f = tid + i * 256;
            int row = f >> 3, c16 = (f & 7) * 8;
            CP_ASYNC16(sBu[buf] + (uint32_t)(row * LDTH + c16) * 2,
                       bp + (size_t)row * GK + c16);
        }
    };

    load_chunk(0, 0);
    CP_COMMIT();

    for (int c = 0; c < GNCHUNK; ++c) {
        const int b = c & 1;
        if (c + 1 < GNCHUNK) {
            load_chunk(c + 1, b ^ 1);
            CP_COMMIT();
            CP_WAIT1();
        } else {
            CP_WAIT0();
        }
        __syncthreads();

        const __half* As = sA[b];
        const __half* Bs = sB[b];
#pragma unroll
        for (int ks = 0; ks < 4; ++ks) {              // 4 k16-steps per BK=64
            const int k2 = ks * 16 + 2 * t4;
            uint32_t af[4][4], bf[4][2];
#pragma unroll
            for (int mi = 0; mi < 4; ++mi) {
                const int r = wm + mi * 16 + g;
                af[mi][0] = *reinterpret_cast<const uint32_t*>(&As[r * LDTH + k2]);
                af[mi][1] = *reinterpret_cast<const uint32_t*>(&As[(r + 8) * LDTH + k2]);
                af[mi][2] = *reinterpret_cast<const uint32_t*>(&As[r * LDTH + k2 + 8]);
                af[mi][3] = *reinterpret_cast<const uint32_t*>(&As[(r + 8) * LDTH + k2 + 8]);
            }
#pragma unroll
            for (int ni = 0; ni < 4; ++ni) {
                const int n = wn + ni * 8 + g;
                bf[ni][0] = *reinterpret_cast<const uint32_t*>(&Bs[n * LDTH + k2]);
                bf[ni][1] = *reinterpret_cast<const uint32_t*>(&Bs[n * LDTH + k2 + 8]);
            }
#pragma unroll
            for (int mi = 0; mi < 4; ++mi)
#pragma unroll
                for (int ni = 0; ni < 4; ++ni)
                    mma_f16(acc[mi][ni], af[mi], bf[ni]);
        }
        __syncthreads();
    }

    // epilogue
#pragma unroll
    for (int mi = 0; mi < 4; ++mi) {
#pragma unroll
        for (int ni = 0; ni < 4; ++ni) {
            const int row = bm + wm + mi * 16 + g;
            const int col = bn + wn + ni * 8 + t4 * 2;
            const float b0 = __ldg(&bias[col]), b1 = __ldg(&bias[col + 1]);
            float v00 = acc[mi][ni][0] + b0, v01 = acc[mi][ni][1] + b1;
            float v10 = acc[mi][ni][2] + b0, v11 = acc[mi][ni][3] + b1;
            if (OUT_FLOAT) {
                float* C = reinterpret_cast<float*>(Cout);
                *reinterpret_cast<float2*>(&C[(size_t)row * Ntot + col])       = make_float2(v00, v01);
                *reinterpret_cast<float2*>(&C[(size_t)(row + 8) * Ntot + col]) = make_float2(v10, v11);
            } else {
                __half* C = reinterpret_cast<__half*>(Cout);
                *reinterpret_cast<uint32_t*>(&C[(size_t)row * Ntot + col])       = pack_h2(v00, v01);
                *reinterpret_cast<uint32_t*>(&C[(size_t)(row + 8) * Ntot + col]) = pack_h2(v10, v11);
            }
        }
    }
}

// ======================= fp16 flash attention ===============================
// grid (12, 256, 3), block 128 (4 warps). Warp owns 32 query rows; block owns
// 128 rows (3 row-tiles cover 384 >= 343). KV chunks of 64 keys.
// S-fragment (fp32) -> f16x2 A-fragment directly in registers (no smem P).
#define AT_THREADS 128
#define LDKH 40     // Ks stride (32 hd + 8 pad) halves
#define LDVT 72     // Vt stride (64 keys + 8 pad) halves

__global__ __launch_bounds__(AT_THREADS, 1) void attn_f16_kernel(
    const __half* __restrict__ qkv, const __half* __restrict__ biasP,
    __half* __restrict__ out)
{
    __shared__ __half Ks[64 * LDKH];   // [key][hd]
    __shared__ __half Vt[32 * LDVT];   // [hd][key]
    const int h   = blockIdx.x;
    const int b   = blockIdx.y;
    const int tid = threadIdx.x;
    const int wid = tid >> 5, lid = tid & 31;
    const int g = lid >> 2, t4 = lid & 3;
    const int wm = blockIdx.z * 128 + wid * 32;
    const __half* base = qkv + (size_t)b * NTOK * QKVC;
    const float scale = 0.17677669529663687f;
    const uint32_t KsU = smem_u32(Ks);

    // ---- Q a-frags straight from global (half2 loads) ---------------------
    uint32_t qa[2][2][4];
#pragma unroll
    for (int mi = 0; mi < 2; ++mi) {
        const int r0 = wm + mi * 16 + g, r1 = r0 + 8;
        const __half* q0 = base + (size_t)r0 * QKVC + h * HDIM;
        const __half* q1 = base + (size_t)r1 * QKVC + h * HDIM;
#pragma unroll
        for (int ks = 0; ks < 2; ++ks) {
            const int k2 = ks * 16 + 2 * t4;
            qa[mi][ks][0] = (r0 < NTOK) ? *reinterpret_cast<const uint32_t*>(q0 + k2) : 0u;
            qa[mi][ks][1] = (r1 < NTOK) ? *reinterpret_cast<const uint32_t*>(q1 + k2) : 0u;
            qa[mi][ks][2] = (r0 < NTOK) ? *reinterpret_cast<const uint32_t*>(q0 + k2 + 8) : 0u;
            qa[mi][ks][3] = (r1 < NTOK) ? *reinterpret_cast<const uint32_t*>(q1 + k2 + 8) : 0u;
        }
    }

    float o[2][4][4];
#pragma unroll
    for (int mi = 0; mi < 2; ++mi)
#pragma unroll
        for (int n = 0; n < 4; ++n)
#pragma unroll
            for (int q = 0; q < 4; ++q) o[mi][n][q] = 0.f;
    float mrow[2][2] = {{-1e30f, -1e30f}, {-1e30f, -1e30f}};
    float lrow[2][2] = {{0.f, 0.f}, {0.f, 0.f}};

    const __half* bp = biasP + ((size_t)h * NPAD + wm) * KPAD;

    for (int ch = 0; ch < 6; ++ch) {
        const int j0 = ch * 64;
        __syncthreads();
        // ---- K tile via cp.async (zero-fill pad keys) ---------------------
#pragma unroll
        for (int i = 0; i < 2; ++i) {
            int f = tid + i * 128;                     // 256 slots
            int row = f >> 2, c16 = (f & 3) * 8;
            int kr = j0 + row;
            const __half* src = base + (size_t)kr * QKVC + CDIM + h * HDIM + c16;
            CP_ASYNC16P(KsU + (uint32_t)(row * LDKH + c16) * 2, src,
                        (kr < NTOK) ? 16u : 0u);
        }
        CP_COMMIT();
        // ---- V tile transposed: Vt[hd][key] -------------------------------
#pragma unroll
        for (int i = 0; i < 8; ++i) {
            int f = tid + i * 128;                     // 1024 units
            int key = f >> 4, hp = (f & 15) * 2;
            int kr = j0 + key;
            uint32_t val = 0;
            if (kr < NTOK)
                val = *reinterpret_cast<const uint32_t*>(
                    base + (size_t)kr * QKVC + 2 * CDIM + h * HDIM + hp);
            __half2 hv = *reinterpret_cast<__half2*>(&val);
            Vt[hp * LDVT + key]       = __low2half(hv);
            Vt[(hp + 1) * LDVT + key] = __high2half(hv);
        }
        CP_WAIT0();
        __syncthreads();

        // ---- S = Q K^T (fp32 accum, init 0) -------------------------------
        float c[2][8][4];
#pragma unroll
        for (int mi = 0; mi < 2; ++mi)
#pragma unroll
            for (int ni = 0; ni < 8; ++ni)
#pragma unroll
                for (int q = 0; q < 4; ++q) c[mi][ni][q] = 0.f;
#pragma unroll
        for (int ks = 0; ks < 2; ++ks) {
            const int k2 = ks * 16 + 2 * t4;
            uint32_t kb[8][2];
#pragma unroll
            for (int ni = 0; ni < 8; ++ni) {
                kb[ni][0] = *reinterpret_cast<const uint32_t*>(&Ks[(ni * 8 + g) * LDKH + k2]);
                kb[ni][1] = *reinterpret_cast<const uint32_t*>(&Ks[(ni * 8 + g) * LDKH + k2 + 8]);
            }
#pragma unroll
            for (int mi = 0; mi < 2; ++mi)
#pragma unroll
                for (int ni = 0; ni < 8; ++ni)
                    mma_f16(c[mi][ni], qa[mi][ks], kb[ni]);
        }
        // ---- scale + bias -------------------------------------------------
#pragma unroll
        for (int mi = 0; mi < 2; ++mi) {
            const __half* b0p = bp + (size_t)(mi * 16 + g) * KPAD + j0 + 2 * t4;
            const __half* b1p = bp + (size_t)(mi * 16 + 8 + g) * KPAD + j0 + 2 * t4;
#pragma unroll
            for (int ni = 0; ni < 8; ++ni) {
                float2 bb0 = __half22float2(*reinterpret_cast<const __half2*>(b0p + ni * 8));
                float2 bb1 = __half22float2(*reinterpret_cast<const __half2*>(b1p + ni * 8));
                c[mi][ni][0] = c[mi][ni][0] * scale + bb0.x;
                c[mi][ni][1] = c[mi][ni][1] * scale + bb0.y;
                c[mi][ni][2] = c[mi][ni][2] * scale + bb1.x;
                c[mi][ni][3] = c[mi][ni][3] * scale + bb1.y;
            }
        }

        // ---- online softmax ----------------------------------------------
#pragma unroll
        for (int mi = 0; mi < 2; ++mi) {
            float mx0 = c[mi][0][0], mx1 = c[mi][0][2];
#pragma unroll
            for (int ni = 0; ni < 8; ++ni) {
                mx0 = fmaxf(mx0, fmaxf(c[mi][ni][0], c[mi][ni][1]));
                mx1 = fmaxf(mx1, fmaxf(c[mi][ni][2], c[mi][ni][3]));
            }
            mx0 = fmaxf(mx0, __shfl_xor_sync(0xFFFFFFFF, mx0, 1));
            mx0 = fmaxf(mx0, __shfl_xor_sync(0xFFFFFFFF, mx0, 2));
            mx1 = fmaxf(mx1, __shfl_xor_sync(0xFFFFFFFF, mx1, 1));
            mx1 = fmaxf(mx1, __shfl_xor_sync(0xFFFFFFFF, mx1, 2));
            float nm0 = fmaxf(mrow[mi][0], mx0);
            float nm1 = fmaxf(mrow[mi][1], mx1);
            float cr0 = __expf(mrow[mi][0] - nm0);
            float cr1 = __expf(mrow[mi][1] - nm1);
            mrow[mi][0] = nm0; mrow[mi][1] = nm1;
#pragma unroll
            for (int n = 0; n < 4; ++n) {
                o[mi][n][0] *= cr0; o[mi][n][1] *= cr0;
                o[mi][n][2] *= cr1; o[mi][n][3] *= cr1;
            }
            float s0 = 0.f, s1 = 0.f;
#pragma unroll
            for (int ni = 0; ni < 8; ++ni) {
                c[mi][ni][0] = __expf(c[mi][ni][0] - nm0); s0 += c[mi][ni][0];
                c[mi][ni][1] = __expf(c[mi][ni][1] - nm0); s0 += c[mi][ni][1];
                c[mi][ni][2] = __expf(c[mi][ni][2] - nm1); s1 += c[mi][ni][2];
                c[mi][ni][3] = __expf(c[mi][ni][3] - nm1); s1 += c[mi][ni][3];
            }
            s0 += __shfl_xor_sync(0xFFFFFFFF, s0, 1);
            s0 += __shfl_xor_sync(0xFFFFFFFF, s0, 2);
            s1 += __shfl_xor_sync(0xFFFFFFFF, s1, 1);
            s1 += __shfl_xor_sync(0xFFFFFFFF, s1, 2);
            lrow[mi][0] = lrow[mi][0] * cr0 + s0;
            lrow[mi][1] = lrow[mi][1] * cr1 + s1;
        }

        // ---- O += P V : P frags from registers (fp16 layout match) --------
#pragma unroll
        for (int grp = 0; grp < 4; ++grp) {
            uint32_t vb[4][2];
#pragma unroll
            for (int n = 0; n < 4; ++n) {
                vb[n][0] = *reinterpret_cast<const uint32_t*>(&Vt[(n * 8 + g) * LDVT + grp * 16 + 2 * t4]);
                vb[n][1] = *reinterpret_cast<const uint32_t*>(&Vt[(n * 8 + g) * LDVT + grp * 16 + 2 * t4 + 8]);
            }
#pragma unroll
            for (int mi = 0; mi < 2; ++mi) {
                uint32_t pa[4];
                pa[0] = pack_h2(c[mi][2 * grp][0],     c[mi][2 * grp][1]);
                pa[1] = pack_h2(c[mi][2 * grp][2],     c[mi][2 * grp][3]);
                pa[2] = pack_h2(c[mi][2 * grp + 1][0], c[mi][2 * grp + 1][1]);
                pa[3] = pack_h2(c[mi][2 * grp + 1][2], c[mi][2 * grp + 1][3]);
#pragma unroll
                for (int n = 0; n < 4; ++n)
                    mma_f16(o[mi][n], pa, vb[n]);
            }
        }
    }

    // ---- normalize + store half -------------------------------------------
#pragma unroll
    for (int mi = 0; mi < 2; ++mi) {
        const float i0 = 1.f / lrow[mi][0];
        const float i1 = 1.f / lrow[mi][1];
        const int r0 = wm + mi * 16 + g;
        const int r1 = r0 + 8;
        if (r0 < NTOK) {
            __half* op = out + ((size_t)b * NTOK + r0) * CDIM + h * HDIM + 2 * t4;
#pragma unroll
            for (int n = 0; n < 4; ++n)
                *reinterpret_cast<uint32_t*>(op + n * 8) =
                    pack_h2(o[mi][n][0] * i0, o[mi][n][1] * i0);
        }
        if (r1 < NTOK) {
            __half* op = out + ((size_t)b * NTOK + r1) * CDIM + h * HDIM + 2 * t4;
#pragma unroll
            for (int n = 0; n < 4; ++n)
                *reinterpret_cast<uint32_t*>(op + n * 8) =
                    pack_h2(o[mi][n][2] * i1, o[mi][n][3] * i1);
        }
    }
}

// ---------------- launch ------------------------------------------------------
extern "C" void kernel_launch(void* const* d_in, const int* in_sizes, int n_in,
                              void* d_out, int out_size)
{
    const float* x       = (const float*)d_in[0];
    const float* qkv_w   = (const float*)d_in[1];
    const float* qkv_b   = (const float*)d_in[2];
    const float* proj_w  = (const float*)d_in[3];
    const float* proj_b  = (const float*)d_in[4];
    const float* bt      = (const float*)d_in[5];
    const int*   ridx    = (const int*)d_in[6];
    float*       out     = (float*)d_out;

    void *p_qkv, *p_att, *p_bias, *p_xh, *p_wqt, *p_wpt;
    cudaGetSymbolAddress(&p_qkv,  g_qkv);
    cudaGetSymbolAddress(&p_att,  g_att);
    cudaGetSymbolAddress(&p_bias, g_biasH);
    cudaGetSymbolAddress(&p_xh,   g_xh);
    cudaGetSymbolAddress(&p_wqt,  g_wqt);
    cudaGetSymbolAddress(&p_wpt,  g_wpt);
    __half* qkvh = (__half*)p_qkv;
    __half* atth = (__half*)p_att;
    __half* bias = (__half*)p_bias;
    __half* xh   = (__half*)p_xh;
    __half* wqt  = (__half*)p_wqt;
    __half* wpt  = (__half*)p_wpt;

    cudaFuncSetAttribute(mma_gemm_h<false>,
                         cudaFuncAttributeMaxDynamicSharedMemorySize, GSM_TOT);
    cudaFuncSetAttribute(mma_gemm_h<true>,
                         cudaFuncAttributeMaxDynamicSharedMemorySize, GSM_TOT);

    // 0) prep: x -> half; transpose weights -> half; expand padded bias (half)
    {
        int n4 = MROWS * CDIM / 4;
        f32_to_h_kernel<<<(n4 + 255) / 256, 256>>>(x, xh, n4);
        transpose_h_kernel<<<dim3(QKVC / 32, CDIM / 32), dim3(32, 8)>>>(qkv_w, wqt, CDIM, QKVC);
        transpose_h_kernel<<<dim3(CDIM / 32, CDIM / 32), dim3(32, 8)>>>(proj_w, wpt, CDIM, CDIM);
        int total = NHEADS * NPAD * KPAD;
        bias_expand_h_kernel<<<(total + 255) / 256, 256>>>(bt, ridx, bias);
    }

    // 1) QKV projection (fp16 mma, half output)
    mma_gemm_h<false><<<dim3(QKVC / 128, MROWS / 128), 256, GSM_TOT>>>(
        xh, wqt, qkv_b, qkvh, QKVC);

    // 2) fp16 flash attention (half output)
    attn_f16_kernel<<<dim3(NHEADS, NWIN, 3), AT_THREADS>>>(qkvh, bias, atth);

    // 3) output projection (fp16 mma, fp32 output)
    mma_gemm_h<true><<<dim3(CDIM / 128, MROWS / 128), 256, GSM_TOT>>>(
        atth, wpt, proj_b, out, CDIM);
}

// round 9
// speedup vs baseline: 2.2578x; 1.1527x over previous
#include <cuda_runtime.h>
#include <cuda_fp16.h>
#include <cstdint>
#include <cstdio>

#define NTOK   343
#define NWIN   256
#define NHEADS 12
#define HDIM   32
#define CDIM   384
#define MROWS  (NWIN * NTOK)     // 87808
#define QKVC   (3 * CDIM)        // 1152
#define NPAD   384
#define KPAD   384

// ---------------- scratch (static device globals) ---------------------------
__device__ __half g_qkv[(size_t)MROWS * QKVC];
__device__ __half g_att[(size_t)MROWS * CDIM];
__device__ __half g_biasH[NHEADS * NPAD * KPAD];
__device__ __half g_xh[(size_t)MROWS * CDIM];
__device__ __half g_wqt[(size_t)QKVC * CDIM];
__device__ __half g_wpt[(size_t)CDIM * CDIM];

template<int N> struct IC { static constexpr int value = N; };

// ======================= helpers ============================================
__device__ __forceinline__ uint32_t smem_u32(const void* p) {
    uint32_t a;
    asm("{ .reg .u64 t; cvta.to.shared.u64 t, %1; cvt.u32.u64 %0, t; }" : "=r"(a) : "l"(p));
    return a;
}
__device__ __forceinline__ uint32_t pack_h2(float lo, float hi) {
    uint32_t r;
    asm("cvt.rn.f16x2.f32 %0, %1, %2;" : "=r"(r) : "f"(hi), "f"(lo));
    return r;
}
__device__ __forceinline__ void ldsm_x4(uint32_t& r0, uint32_t& r1, uint32_t& r2,
                                        uint32_t& r3, uint32_t addr) {
    asm volatile("ldmatrix.sync.aligned.m8n8.x4.shared.b16 {%0,%1,%2,%3}, [%4];"
                 : "=r"(r0), "=r"(r1), "=r"(r2), "=r"(r3) : "r"(addr));
}
#define CP_ASYNC16(dst, src) \
    asm volatile("cp.async.cg.shared.global [%0], [%1], 16;" :: "r"(dst), "l"(src))
#define CP_ASYNC16P(dst, src, n) \
    asm volatile("cp.async.cg.shared.global [%0], [%1], 16, %2;" :: "r"(dst), "l"(src), "r"(n))
#define CP_COMMIT() asm volatile("cp.async.commit_group;" ::: "memory")
#define CP_WAIT1()  asm volatile("cp.async.wait_group 1;" ::: "memory")
#define CP_WAIT0()  asm volatile("cp.async.wait_group 0;" ::: "memory")

__device__ __forceinline__ void mma_f16(float* c, const uint32_t* a, const uint32_t* b) {
    asm volatile(
        "mma.sync.aligned.m16n8k16.row.col.f32.f16.f16.f32 "
        "{%0,%1,%2,%3}, {%4,%5,%6,%7}, {%8,%9}, {%0,%1,%2,%3};"
        : "+f"(c[0]), "+f"(c[1]), "+f"(c[2]), "+f"(c[3])
        : "r"(a[0]), "r"(a[1]), "r"(a[2]), "r"(a[3]), "r"(b[0]), "r"(b[1]));
}

// ======================= prep kernels =======================================
__global__ void f32_to_h_kernel(const float* __restrict__ in, __half* __restrict__ out, int n4) {
    int i = blockIdx.x * blockDim.x + threadIdx.x;
    if (i < n4) {
        float4 v = reinterpret_cast<const float4*>(in)[i];
        uint2 o;
        o.x = pack_h2(v.x, v.y);
        o.y = pack_h2(v.z, v.w);
        reinterpret_cast<uint2*>(out)[i] = o;
    }
}

__global__ void transpose_h_kernel(const float* __restrict__ W, __half* __restrict__ Wt,
                                   int K, int Nw) {
    __shared__ float t[32][33];
    int n0 = blockIdx.x * 32, k0 = blockIdx.y * 32;
#pragma unroll
    for (int s = 0; s < 4; ++s) {
        int k = k0 + threadIdx.y + s * 8;
        t[threadIdx.y + s * 8][threadIdx.x] = W[(size_t)k * Nw + n0 + threadIdx.x];
    }
    __syncthreads();
#pragma unroll
    for (int s = 0; s < 4; ++s) {
        int n = n0 + threadIdx.y + s * 8;
        Wt[(size_t)n * K + k0 + threadIdx.x] = __float2half(t[threadIdx.x][threadIdx.y + s * 8]);
    }
}

__global__ void bias_expand_h_kernel(const float* __restrict__ bt,
                                     const int* __restrict__ ridx,
                                     __half* __restrict__ bf)
{
    int idx = blockIdx.x * blockDim.x + threadIdx.x;
    if (idx < NHEADS * NPAD * KPAD) {
        int h   = idx / (NPAD * KPAD);
        int rem = idx - h * NPAD * KPAD;
        int r   = rem / KPAD;
        int k   = rem - r * KPAD;
        float v;
        if (k >= NTOK)      v = -60000.f;
        else if (r >= NTOK) v = 0.f;
        else                v = bt[ridx[r * NTOK + k] * NHEADS + h];
        bf[idx] = __float2half(v);
    }
}

// ======================= fp16 mma GEMM (ldmatrix frags) =====================
#define GK       384
#define GNCHUNK  6
#define LDTH     72
#define GTILE_H  (128 * LDTH)
#define GSM_TOT  (4 * GTILE_H * 2)

template<bool OUT_FLOAT>
__global__ __launch_bounds__(256, 2) void mma_gemm_h(
    const __half* __restrict__ A, const __half* __restrict__ Wt,
    const float* __restrict__ bias, void* __restrict__ Cout, int Ntot)
{
    extern __shared__ __half smh[];
    __half* sA[2] = { smh,               smh + GTILE_H };
    __half* sB[2] = { smh + 2 * GTILE_H, smh + 3 * GTILE_H };
    const uint32_t sAu[2] = { smem_u32(sA[0]), smem_u32(sA[1]) };
    const uint32_t sBu[2] = { smem_u32(sB[0]), smem_u32(sB[1]) };

    const int tid = threadIdx.x;
    const int wid = tid >> 5, lid = tid & 31;
    const int g = lid >> 2, t4 = lid & 3;
    const int grp4 = lid >> 3;
    const int wm = (wid & 1) * 64;
    const int wn = (wid >> 1) * 32;
    const int bm = blockIdx.y * 128;
    const int bn = blockIdx.x * 128;

    // ldmatrix per-lane offsets (bytes)
    const uint32_t aOff = (uint32_t)((wm + (grp4 & 1) * 8 + (lid & 7)) * LDTH
                                     + (grp4 >> 1) * 8) * 2;
    const uint32_t bOff = (uint32_t)((wn + (grp4 >> 1) * 8 + (lid & 7)) * LDTH
                                     + (grp4 & 1) * 8) * 2;

    float acc[4][4][4];
#pragma unroll
    for (int i = 0; i < 4; ++i)
#pragma unroll
        for (int j = 0; j < 4; ++j)
#pragma unroll
            for (int q = 0; q < 4; ++q) acc[i][j][q] = 0.f;

    auto load_chunk = [&](int c, int buf) {
        const __half* ap = A  + (size_t)bm * GK + c * 64;
        const __half* bp = Wt + (size_t)bn * GK + c * 64;
#pragma unroll
        for (int i = 0; i < 4; ++i) {
            int f = tid + i * 256;
            int row = f >> 3, c16 = (f & 7) * 8;
            CP_ASYNC16(sAu[buf] + (uint32_t)(row * LDTH + c16) * 2,
                       ap + (size_t)row * GK + c16);
        }
#pragma unroll
        for (int i = 0; i < 4; ++i) {
            int f = tid + i * 256;
            int row = f >> 3, c16 = (f & 7) * 8;
            CP_ASYNC16(sBu[buf] + (uint32_t)(row * LDTH + c16) * 2,
                       bp + (size_t)row * GK + c16);
        }
    };

    load_chunk(0, 0);
    CP_COMMIT();

    for (int c = 0; c < GNCHUNK; ++c) {
        const int b = c & 1;
        if (c + 1 < GNCHUNK) {
            load_chunk(c + 1, b ^ 1);
            CP_COMMIT();
            CP_WAIT1();
        } else {
            CP_WAIT0();
        }
        __syncthreads();

#pragma unroll
        for (int ks = 0; ks < 4; ++ks) {
            uint32_t af[4][4], bf[4][2];
#pragma unroll
            for (int mi = 0; mi < 4; ++mi)
                ldsm_x4(af[mi][0], af[mi][1], af[mi][2], af[mi][3],
                        sAu[b] + aOff + (uint32_t)(mi * 16 * LDTH * 2 + ks * 32));
            ldsm_x4(bf[0][0], bf[0][1], bf[1][0], bf[1][1],
                    sBu[b] + bOff + (uint32_t)(ks * 32));
            ldsm_x4(bf[2][0], bf[2][1], bf[3][0], bf[3][1],
                    sBu[b] + bOff + (uint32_t)(16 * LDTH * 2 + ks * 32));
#pragma unroll
            for (int mi = 0; mi < 4; ++mi)
#pragma unroll
                for (int ni = 0; ni < 4; ++ni)
                    mma_f16(acc[mi][ni], af[mi], bf[ni]);
        }
        __syncthreads();
    }

#pragma unroll
    for (int mi = 0; mi < 4; ++mi) {
#pragma unroll
        for (int ni = 0; ni < 4; ++ni) {
            const int row = bm + wm + mi * 16 + g;
            const int col = bn + wn + ni * 8 + t4 * 2;
            const float b0 = __ldg(&bias[col]), b1 = __ldg(&bias[col + 1]);
            float v00 = acc[mi][ni][0] + b0, v01 = acc[mi][ni][1] + b1;
            float v10 = acc[mi][ni][2] + b0, v11 = acc[mi][ni][3] + b1;
            if (OUT_FLOAT) {
                float* C = reinterpret_cast<float*>(Cout);
                *reinterpret_cast<float2*>(&C[(size_t)row * Ntot + col])       = make_float2(v00, v01);
                *reinterpret_cast<float2*>(&C[(size_t)(row + 8) * Ntot + col]) = make_float2(v10, v11);
            } else {
                __half* C = reinterpret_cast<__half*>(Cout);
                *reinterpret_cast<uint32_t*>(&C[(size_t)row * Ntot + col])       = pack_h2(v00, v01);
                *reinterpret_cast<uint32_t*>(&C[(size_t)(row + 8) * Ntot + col]) = pack_h2(v10, v11);
            }
        }
    }
}

// ======================= fp16 flash attention ===============================
#define AT_THREADS 128
#define LDKH 40
#define LDVT 72

__global__ __launch_bounds__(AT_THREADS, 1) void attn_f16_kernel(
    const __half* __restrict__ qkv, const __half* __restrict__ biasP,
    __half* __restrict__ out)
{
    __shared__ __half Ks[64 * LDKH];
    __shared__ __half Vt[32 * LDVT];
    const int h   = blockIdx.x;
    const int b   = blockIdx.y;
    const int tid = threadIdx.x;
    const int wid = tid >> 5, lid = tid & 31;
    const int g = lid >> 2, t4 = lid & 3;
    const int grp4 = lid >> 3;
    const int wm = blockIdx.z * 128 + wid * 32;
    const bool active = wm < NTOK;
    const __half* base = qkv + (size_t)b * NTOK * QKVC;
    const float scale = 0.17677669529663687f;
    const uint32_t KsU = smem_u32(Ks), VtU = smem_u32(Vt);

    // ldmatrix lane offsets
    const uint32_t kOff = (uint32_t)(((grp4 >> 1) * 8 + (lid & 7)) * LDKH
                                     + (grp4 & 1) * 8) * 2;
    const uint32_t vOff = (uint32_t)(((grp4 >> 1) * 8 + (lid & 7)) * LDVT
                                     + (grp4 & 1) * 8) * 2;

    // ---- Q a-frags straight from global ----------------------------------
    uint32_t qa[2][2][4];
#pragma unroll
    for (int mi = 0; mi < 2; ++mi) {
        const int r0 = wm + mi * 16 + g, r1 = r0 + 8;
        const __half* q0 = base + (size_t)r0 * QKVC + h * HDIM;
        const __half* q1 = base + (size_t)r1 * QKVC + h * HDIM;
#pragma unroll
        for (int ks = 0; ks < 2; ++ks) {
            const int k2 = ks * 16 + 2 * t4;
            qa[mi][ks][0] = (r0 < NTOK) ? *reinterpret_cast<const uint32_t*>(q0 + k2) : 0u;
            qa[mi][ks][1] = (r1 < NTOK) ? *reinterpret_cast<const uint32_t*>(q1 + k2) : 0u;
            qa[mi][ks][2] = (r0 < NTOK) ? *reinterpret_cast<const uint32_t*>(q0 + k2 + 8) : 0u;
            qa[mi][ks][3] = (r1 < NTOK) ? *reinterpret_cast<const uint32_t*>(q1 + k2 + 8) : 0u;
        }
    }

    float o[2][4][4];
#pragma unroll
    for (int mi = 0; mi < 2; ++mi)
#pragma unroll
        for (int n = 0; n < 4; ++n)
#pragma unroll
            for (int q = 0; q < 4; ++q) o[mi][n][q] = 0.f;
    float mrow[2][2] = {{-1e30f, -1e30f}, {-1e30f, -1e30f}};
    float lrow[2][2] = {{0.f, 0.f}, {0.f, 0.f}};

    const __half* bp = biasP + ((size_t)h * NPAD + wm) * KPAD;

    auto chunk = [&](auto NIc, auto NGRPc, int ch) {
        constexpr int NI   = decltype(NIc)::value;    // active n8 key tiles
        constexpr int NGRP = decltype(NGRPc)::value;  // active 16-key PV groups
        const int j0 = ch * 64;
        __syncthreads();
        // ---- K tile via cp.async (zero-fill pad keys) ---------------------
#pragma unroll
        for (int i = 0; i < 2; ++i) {
            int f = tid + i * 128;
            int row = f >> 2, c16 = (f & 3) * 8;
            int kr = j0 + row;
            const __half* src = base + (size_t)kr * QKVC + CDIM + h * HDIM + c16;
            CP_ASYNC16P(KsU + (uint32_t)(row * LDKH + c16) * 2, src,
                        (kr < NTOK) ? 16u : 0u);
        }
        CP_COMMIT();
        // ---- V tile transposed --------------------------------------------
#pragma unroll
        for (int i = 0; i < 8; ++i) {
            int f = tid + i * 128;
            int key = f >> 4, hp = (f & 15) * 2;
            int kr = j0 + key;
            uint32_t val = 0;
            if (kr < NTOK)
                val = *reinterpret_cast<const uint32_t*>(
                    base + (size_t)kr * QKVC + 2 * CDIM + h * HDIM + hp);
            __half2 hv = *reinterpret_cast<__half2*>(&val);
            Vt[hp * LDVT + key]       = __low2half(hv);
            Vt[(hp + 1) * LDVT + key] = __high2half(hv);
        }
        CP_WAIT0();
        __syncthreads();

        if (!active) return;

        // ---- S = Q K^T ----------------------------------------------------
        float c[2][8][4];
#pragma unroll
        for (int mi = 0; mi < 2; ++mi)
#pragma unroll
            for (int ni = 0; ni < NI; ++ni)
#pragma unroll
                for (int q = 0; q < 4; ++q) c[mi][ni][q] = 0.f;
#pragma unroll
        for (int ks = 0; ks < 2; ++ks) {
            uint32_t kb[8][2];
#pragma unroll
            for (int p = 0; p < (NI + 1) / 2; ++p)
                ldsm_x4(kb[2*p][0], kb[2*p][1], kb[2*p+1][0], kb[2*p+1][1],
                        KsU + kOff + (uint32_t)(p * 16 * LDKH * 2 + ks * 32));
#pragma unroll
            for (int mi = 0; mi < 2; ++mi)
#pragma unroll
                for (int ni = 0; ni < NI; ++ni)
                    mma_f16(c[mi][ni], qa[mi][ks], kb[ni]);
        }
        // ---- scale + bias -------------------------------------------------
#pragma unroll
        for (int mi = 0; mi < 2; ++mi) {
            const __half* b0p = bp + (size_t)(mi * 16 + g) * KPAD + j0 + 2 * t4;
            const __half* b1p = bp + (size_t)(mi * 16 + 8 + g) * KPAD + j0 + 2 * t4;
#pragma unroll
            for (int ni = 0; ni < NI; ++ni) {
                float2 bb0 = __half22float2(*reinterpret_cast<const __half2*>(b0p + ni * 8));
                float2 bb1 = __half22float2(*reinterpret_cast<const __half2*>(b1p + ni * 8));
                c[mi][ni][0] = c[mi][ni][0] * scale + bb0.x;
                c[mi][ni][1] = c[mi][ni][1] * scale + bb0.y;
                c[mi][ni][2] = c[mi][ni][2] * scale + bb1.x;
                c[mi][ni][3] = c[mi][ni][3] * scale + bb1.y;
            }
        }
        // ---- online softmax ----------------------------------------------
#pragma unroll
        for (int mi = 0; mi < 2; ++mi) {
            float mx0 = c[mi][0][0], mx1 = c[mi][0][2];
#pragma unroll
            for (int ni = 0; ni < NI; ++ni) {
                mx0 = fmaxf(mx0, fmaxf(c[mi][ni][0], c[mi][ni][1]));
                mx1 = fmaxf(mx1, fmaxf(c[mi][ni][2], c[mi][ni][3]));
            }
            mx0 = fmaxf(mx0, __shfl_xor_sync(0xFFFFFFFF, mx0, 1));
            mx0 = fmaxf(mx0, __shfl_xor_sync(0xFFFFFFFF, mx0, 2));
            mx1 = fmaxf(mx1, __shfl_xor_sync(0xFFFFFFFF, mx1, 1));
            mx1 = fmaxf(mx1, __shfl_xor_sync(0xFFFFFFFF, mx1, 2));
            float nm0 = fmaxf(mrow[mi][0], mx0);
            float nm1 = fmaxf(mrow[mi][1], mx1);
            float cr0 = __expf(mrow[mi][0] - nm0);
            float cr1 = __expf(mrow[mi][1] - nm1);
            mrow[mi][0] = nm0; mrow[mi][1] = nm1;
#pragma unroll
            for (int n = 0; n < 4; ++n) {
                o[mi][n][0] *= cr0; o[mi][n][1] *= cr0;
                o[mi][n][2] *= cr1; o[mi][n][3] *= cr1;
            }
            float s0 = 0.f, s1 = 0.f;
#pragma unroll
            for (int ni = 0; ni < NI; ++ni) {
                c[mi][ni][0] = __expf(c[mi][ni][0] - nm0); s0 += c[mi][ni][0];
                c[mi][ni][1] = __expf(c[mi][ni][1] - nm0); s0 += c[mi][ni][1];
                c[mi][ni][2] = __expf(c[mi][ni][2] - nm1); s1 += c[mi][ni][2];
                c[mi][ni][3] = __expf(c[mi][ni][3] - nm1); s1 += c[mi][ni][3];
            }
            s0 += __shfl_xor_sync(0xFFFFFFFF, s0, 1);
            s0 += __shfl_xor_sync(0xFFFFFFFF, s0, 2);
            s1 += __shfl_xor_sync(0xFFFFFFFF, s1, 1);
            s1 += __shfl_xor_sync(0xFFFFFFFF, s1, 2);
            lrow[mi][0] = lrow[mi][0] * cr0 + s0;
            lrow[mi][1] = lrow[mi][1] * cr1 + s1;
            // zero pad-key tiles consumed by PV groups
#pragma unroll
            for (int ni = NI; ni < 2 * NGRP; ++ni)
#pragma unroll
                for (int q = 0; q < 4; ++q) c[mi][ni][q] = 0.f;
        }
        // ---- O += P V -----------------------------------------------------
#pragma unroll
        for (int grp = 0; grp < NGRP; ++grp) {
            uint32_t vb[4][2];
            ldsm_x4(vb[0][0], vb[0][1], vb[1][0], vb[1][1],
                    VtU + vOff + (uint32_t)(grp * 32));
            ldsm_x4(vb[2][0], vb[2][1], vb[3][0], vb[3][1],
                    VtU + vOff + (uint32_t)(16 * LDVT * 2 + grp * 32));
#pragma unroll
            for (int mi = 0; mi < 2; ++mi) {
                uint32_t pa[4];
                pa[0] = pack_h2(c[mi][2 * grp][0],     c[mi][2 * grp][1]);
                pa[1] = pack_h2(c[mi][2 * grp][2],     c[mi][2 * grp][3]);
                pa[2] = pack_h2(c[mi][2 * grp + 1][0], c[mi][2 * grp + 1][1]);
                pa[3] = pack_h2(c[mi][2 * grp + 1][2], c[mi][2 * grp + 1][3]);
#pragma unroll
                for (int n = 0; n < 4; ++n)
                    mma_f16(o[mi][n], pa, vb[n]);
            }
        }
    };

    for (int ch = 0; ch < 5; ++ch) chunk(IC<8>{}, IC<4>{}, ch);
    chunk(IC<3>{}, IC<2>{}, 5);   // keys 320..343 (+pad): 3 n8 tiles, 2 PV groups

    if (active) {
#pragma unroll
        for (int mi = 0; mi < 2; ++mi) {
            const float i0 = 1.f / lrow[mi][0];
            const float i1 = 1.f / lrow[mi][1];
            const int r0 = wm + mi * 16 + g;
            const int r1 = r0 + 8;
            if (r0 < NTOK) {
                __half* op = out + ((size_t)b * NTOK + r0) * CDIM + h * HDIM + 2 * t4;
#pragma unroll
                for (int n = 0; n < 4; ++n)
                    *reinterpret_cast<uint32_t*>(op + n * 8) =
                        pack_h2(o[mi][n][0] * i0, o[mi][n][1] * i0);
            }
            if (r1 < NTOK) {
                __half* op = out + ((size_t)b * NTOK + r1) * CDIM + h * HDIM + 2 * t4;
#pragma unroll
                for (int n = 0; n < 4; ++n)
                    *reinterpret_cast<uint32_t*>(op + n * 8) =
                        pack_h2(o[mi][n][2] * i1, o[mi][n][3] * i1);
            }
        }
    }
}

// ---------------- launch ------------------------------------------------------
extern "C" void kernel_launch(void* const* d_in, const int* in_sizes, int n_in,
                              void* d_out, int out_size)
{
    const float* x       = (const float*)d_in[0];
    const float* qkv_w   = (const float*)d_in[1];
    const float* qkv_b   = (const float*)d_in[2];
    const float* proj_w  = (const float*)d_in[3];
    const float* proj_b  = (const float*)d_in[4];
    const float* bt      = (const float*)d_in[5];
    const int*   ridx    = (const int*)d_in[6];
    float*       out     = (float*)d_out;

    void *p_qkv, *p_att, *p_bias, *p_xh, *p_wqt, *p_wpt;
    cudaGetSymbolAddress(&p_qkv,  g_qkv);
    cudaGetSymbolAddress(&p_att,  g_att);
    cudaGetSymbolAddress(&p_bias, g_biasH);
    cudaGetSymbolAddress(&p_xh,   g_xh);
    cudaGetSymbolAddress(&p_wqt,  g_wqt);
    cudaGetSymbolAddress(&p_wpt,  g_wpt);
    __half* qkvh = (__half*)p_qkv;
    __half* atth = (__half*)p_att;
    __half* bias = (__half*)p_bias;
    __half* xh   = (__half*)p_xh;
    __half* wqt  = (__half*)p_wqt;
    __half* wpt  = (__half*)p_wpt;

    cudaFuncSetAttribute(mma_gemm_h<false>,
                         cudaFuncAttributeMaxDynamicSharedMemorySize, GSM_TOT);
    cudaFuncSetAttribute(mma_gemm_h<true>,
                         cudaFuncAttributeMaxDynamicSharedMemorySize, GSM_TOT);

    // 0) prep
    {
        int n4 = MROWS * CDIM / 4;
        f32_to_h_kernel<<<(n4 + 255) / 256, 256>>>(x, xh, n4);
        transpose_h_kernel<<<dim3(QKVC / 32, CDIM / 32), dim3(32, 8)>>>(qkv_w, wqt, CDIM, QKVC);
        transpose_h_kernel<<<dim3(CDIM / 32, CDIM / 32), dim3(32, 8)>>>(proj_w, wpt, CDIM, CDIM);
        int total = NHEADS * NPAD * KPAD;
        bias_expand_h_kernel<<<(total + 255) / 256, 256>>>(bt, ridx, bias);
    }

    // 1) QKV projection
    mma_gemm_h<false><<<dim3(QKVC / 128, MROWS / 128), 256, GSM_TOT>>>(
        xh, wqt, qkv_b, qkvh, QKVC);

    // 2) fp16 flash attention
    attn_f16_kernel<<<dim3(NHEADS, NWIN, 3), AT_THREADS>>>(qkvh, bias, atth);

    // 3) output projection
    mma_gemm_h<true><<<dim3(CDIM / 128, MROWS / 128), 256, GSM_TOT>>>(
        atth, wpt, proj_b, out, CDIM);
}

// round 10
// speedup vs baseline: 2.5124x; 1.1128x over previous
#include <cuda_runtime.h>
#include <cuda_fp16.h>
#include <cstdint>
#include <cstdio>

#define NTOK   343
#define NWIN   256
#define NHEADS 12
#define HDIM   32
#define CDIM   384
#define MROWS  (NWIN * NTOK)     // 87808
#define QKVC   (3 * CDIM)        // 1152
#define NPAD   384
#define KPAD   384

// ---------------- scratch (static device globals) ---------------------------
__device__ __half g_qkv[(size_t)MROWS * QKVC];
__device__ __half g_att[(size_t)MROWS * CDIM];
__device__ __half g_biasH[NHEADS * NPAD * KPAD];
__device__ __half g_xh[(size_t)MROWS * CDIM];
__device__ __half g_wqt[(size_t)QKVC * CDIM];
__device__ __half g_wpt[(size_t)CDIM * CDIM];

template<int N> struct IC { static constexpr int value = N; };

// ======================= helpers ============================================
__device__ __forceinline__ uint32_t smem_u32(const void* p) {
    uint32_t a;
    asm("{ .reg .u64 t; cvta.to.shared.u64 t, %1; cvt.u32.u64 %0, t; }" : "=r"(a) : "l"(p));
    return a;
}
__device__ __forceinline__ uint32_t pack_h2(float lo, float hi) {
    uint32_t r;
    asm("cvt.rn.f16x2.f32 %0, %1, %2;" : "=r"(r) : "f"(hi), "f"(lo));
    return r;
}
__device__ __forceinline__ void ldsm_x4(uint32_t& r0, uint32_t& r1, uint32_t& r2,
                                        uint32_t& r3, uint32_t addr) {
    asm volatile("ldmatrix.sync.aligned.m8n8.x4.shared.b16 {%0,%1,%2,%3}, [%4];"
                 : "=r"(r0), "=r"(r1), "=r"(r2), "=r"(r3) : "r"(addr));
}
__device__ __forceinline__ void ldsm_x4_t(uint32_t& r0, uint32_t& r1, uint32_t& r2,
                                          uint32_t& r3, uint32_t addr) {
    asm volatile("ldmatrix.sync.aligned.m8n8.x4.trans.shared.b16 {%0,%1,%2,%3}, [%4];"
                 : "=r"(r0), "=r"(r1), "=r"(r2), "=r"(r3) : "r"(addr));
}
#define CP_ASYNC16(dst, src) \
    asm volatile("cp.async.cg.shared.global [%0], [%1], 16;" :: "r"(dst), "l"(src))
#define CP_ASYNC16P(dst, src, n) \
    asm volatile("cp.async.cg.shared.global [%0], [%1], 16, %2;" :: "r"(dst), "l"(src), "r"(n))
#define CP_COMMIT() asm volatile("cp.async.commit_group;" ::: "memory")
#define CP_WAIT1()  asm volatile("cp.async.wait_group 1;" ::: "memory")
#define CP_WAIT0()  asm volatile("cp.async.wait_group 0;" ::: "memory")

__device__ __forceinline__ void mma_f16(float* c, const uint32_t* a, const uint32_t* b) {
    asm volatile(
        "mma.sync.aligned.m16n8k16.row.col.f32.f16.f16.f32 "
        "{%0,%1,%2,%3}, {%4,%5,%6,%7}, {%8,%9}, {%0,%1,%2,%3};"
        : "+f"(c[0]), "+f"(c[1]), "+f"(c[2]), "+f"(c[3])
        : "r"(a[0]), "r"(a[1]), "r"(a[2]), "r"(a[3]), "r"(b[0]), "r"(b[1]));
}

// ======================= fused prep kernel ==================================
// one launch: x->half | bias expand | qkv_w transpose | proj_w transpose
#define NBX  32928   // MROWS*CDIM/4 / 256
#define NBB  6912    // 12*384*384 / 256
#define NBTQ 432     // (1152/32)*(384/32)
#define NBTP 144     // (384/32)*(384/32)
#define PREP_BLOCKS (NBX + NBB + NBTQ + NBTP)

__global__ __launch_bounds__(256) void prep_kernel(
    const float* __restrict__ x, const float* __restrict__ qkv_w,
    const float* __restrict__ proj_w, const float* __restrict__ bt,
    const int* __restrict__ ridx,
    __half* __restrict__ xh, __half* __restrict__ wqt,
    __half* __restrict__ wpt, __half* __restrict__ bf)
{
    __shared__ float t[32][33];
    const int bid = blockIdx.x;
    const int tid = threadIdx.x;

    if (bid < NBX) {
        int i = bid * 256 + tid;
        float4 v = reinterpret_cast<const float4*>(x)[i];
        uint2 o;
        o.x = pack_h2(v.x, v.y);
        o.y = pack_h2(v.z, v.w);
        reinterpret_cast<uint2*>(xh)[i] = o;
        return;
    }
    if (bid < NBX + NBB) {
        int idx = (bid - NBX) * 256 + tid;
        int h   = idx / (NPAD * KPAD);
        int rem = idx - h * NPAD * KPAD;
        int r   = rem / KPAD;
        int k   = rem - r * KPAD;
        float v;
        if (k >= NTOK)      v = -60000.f;
        else if (r >= NTOK) v = 0.f;
        else                v = bt[ridx[r * NTOK + k] * NHEADS + h];
        bf[idx] = __float2half(v);
        return;
    }
    // transposes: 256 threads as (32 x 8)
    const int tx = tid & 31, ty = tid >> 5;
    const float* W; __half* Wt; int K, Nw, bx, by;
    if (bid < NBX + NBB + NBTQ) {
        int bb = bid - NBX - NBB;
        W = qkv_w; Wt = wqt; K = CDIM; Nw = QKVC;
        bx = bb % (QKVC / 32); by = bb / (QKVC / 32);
    } else {
        int bb = bid - NBX - NBB - NBTQ;
        W = proj_w; Wt = wpt; K = CDIM; Nw = CDIM;
        bx = bb % (CDIM / 32); by = bb / (CDIM / 32);
    }
    int n0 = bx * 32, k0 = by * 32;
#pragma unroll
    for (int s = 0; s < 4; ++s) {
        int k = k0 + ty + s * 8;
        t[ty + s * 8][tx] = W[(size_t)k * Nw + n0 + tx];
    }
    __syncthreads();
#pragma unroll
    for (int s = 0; s < 4; ++s) {
        int n = n0 + ty + s * 8;
        Wt[(size_t)n * K + k0 + tx] = __float2half(t[tx][ty + s * 8]);
    }
}

// ======================= fp16 mma GEMM (ldmatrix frags) =====================
#define GK       384
#define GNCHUNK  6
#define LDTH     72
#define GTILE_H  (128 * LDTH)
#define GSM_TOT  (4 * GTILE_H * 2)

template<bool OUT_FLOAT>
__global__ __launch_bounds__(256, 2) void mma_gemm_h(
    const __half* __restrict__ A, const __half* __restrict__ Wt,
    const float* __restrict__ bias, void* __restrict__ Cout, int Ntot)
{
    extern __shared__ __half smh[];
    __half* sA[2] = { smh,               smh + GTILE_H };
    __half* sB[2] = { smh + 2 * GTILE_H, smh + 3 * GTILE_H };
    const uint32_t sAu[2] = { smem_u32(sA[0]), smem_u32(sA[1]) };
    const uint32_t sBu[2] = { smem_u32(sB[0]), smem_u32(sB[1]) };

    const int tid = threadIdx.x;
    const int wid = tid >> 5, lid = tid & 31;
    const int g = lid >> 2, t4 = lid & 3;
    const int grp4 = lid >> 3;
    const int wm = (wid & 1) * 64;
    const int wn = (wid >> 1) * 32;
    const int bm = blockIdx.y * 128;
    const int bn = blockIdx.x * 128;

    const uint32_t aOff = (uint32_t)((wm + (grp4 & 1) * 8 + (lid & 7)) * LDTH
                                     + (grp4 >> 1) * 8) * 2;
    const uint32_t bOff = (uint32_t)((wn + (grp4 >> 1) * 8 + (lid & 7)) * LDTH
                                     + (grp4 & 1) * 8) * 2;

    float acc[4][4][4];
#pragma unroll
    for (int i = 0; i < 4; ++i)
#pragma unroll
        for (int j = 0; j < 4; ++j)
#pragma unroll
            for (int q = 0; q < 4; ++q) acc[i][j][q] = 0.f;

    auto load_chunk = [&](int c, int buf) {
        const __half* ap = A  + (size_t)bm * GK + c * 64;
        const __half* bp = Wt + (size_t)bn * GK + c * 64;
#pragma unroll
        for (int i = 0; i < 4; ++i) {
            int f = tid + i * 256;
            int row = f >> 3, c16 = (f & 7) * 8;
            CP_ASYNC16(sAu[buf] + (uint32_t)(row * LDTH + c16) * 2,
                       ap + (size_t)row * GK + c16);
        }
#pragma unroll
        for (int i = 0; i < 4; ++i) {
            int f = tid + i * 256;
            int row = f >> 3, c16 = (f & 7) * 8;
            CP_ASYNC16(sBu[buf] + (uint32_t)(row * LDTH + c16) * 2,
                       bp + (size_t)row * GK + c16);
        }
    };

    load_chunk(0, 0);
    CP_COMMIT();

    for (int c = 0; c < GNCHUNK; ++c) {
        const int b = c & 1;
        if (c + 1 < GNCHUNK) {
            load_chunk(c + 1, b ^ 1);
            CP_COMMIT();
            CP_WAIT1();
        } else {
            CP_WAIT0();
        }
        __syncthreads();

#pragma unroll
        for (int ks = 0; ks < 4; ++ks) {
            uint32_t af[4][4], bf[4][2];
#pragma unroll
            for (int mi = 0; mi < 4; ++mi)
                ldsm_x4(af[mi][0], af[mi][1], af[mi][2], af[mi][3],
                        sAu[b] + aOff + (uint32_t)(mi * 16 * LDTH * 2 + ks * 32));
            ldsm_x4(bf[0][0], bf[0][1], bf[1][0], bf[1][1],
                    sBu[b] + bOff + (uint32_t)(ks * 32));
            ldsm_x4(bf[2][0], bf[2][1], bf[3][0], bf[3][1],
                    sBu[b] + bOff + (uint32_t)(16 * LDTH * 2 + ks * 32));
#pragma unroll
            for (int mi = 0; mi < 4; ++mi)
#pragma unroll
                for (int ni = 0; ni < 4; ++ni)
                    mma_f16(acc[mi][ni], af[mi], bf[ni]);
        }
        __syncthreads();
    }

#pragma unroll
    for (int mi = 0; mi < 4; ++mi) {
#pragma unroll
        for (int ni = 0; ni < 4; ++ni) {
            const int row = bm + wm + mi * 16 + g;
            const int col = bn + wn + ni * 8 + t4 * 2;
            const float b0 = __ldg(&bias[col]), b1 = __ldg(&bias[col + 1]);
            float v00 = acc[mi][ni][0] + b0, v01 = acc[mi][ni][1] + b1;
            float v10 = acc[mi][ni][2] + b0, v11 = acc[mi][ni][3] + b1;
            if (OUT_FLOAT) {
                float* C = reinterpret_cast<float*>(Cout);
                *reinterpret_cast<float2*>(&C[(size_t)row * Ntot + col])       = make_float2(v00, v01);
                *reinterpret_cast<float2*>(&C[(size_t)(row + 8) * Ntot + col]) = make_float2(v10, v11);
            } else {
                __half* C = reinterpret_cast<__half*>(Cout);
                *reinterpret_cast<uint32_t*>(&C[(size_t)row * Ntot + col])       = pack_h2(v00, v01);
                *reinterpret_cast<uint32_t*>(&C[(size_t)(row + 8) * Ntot + col]) = pack_h2(v10, v11);
            }
        }
    }
}

// ======================= fp16 flash attention ===============================
// Double-buffered K/V via cp.async; V b-frags via ldmatrix.trans (no scalar
// transpose). grid (12, 256, 3), block 128.
#define AT_THREADS 128
#define LDKH 40

__global__ __launch_bounds__(AT_THREADS, 1) void attn_f16_kernel(
    const __half* __restrict__ qkv, const __half* __restrict__ biasP,
    __half* __restrict__ out)
{
    __shared__ __half Ks[2][64 * LDKH];
    __shared__ __half Vs[2][64 * LDKH];
    const int h   = blockIdx.x;
    const int b   = blockIdx.y;
    const int tid = threadIdx.x;
    const int wid = tid >> 5, lid = tid & 31;
    const int g = lid >> 2, t4 = lid & 3;
    const int grp4 = lid >> 3;
    const int wm = blockIdx.z * 128 + wid * 32;
    const bool active = wm < NTOK;
    const __half* base = qkv + (size_t)b * NTOK * QKVC;
    const float scale = 0.17677669529663687f;
    const uint32_t KsU[2] = { smem_u32(Ks[0]), smem_u32(Ks[1]) };
    const uint32_t VsU[2] = { smem_u32(Vs[0]), smem_u32(Vs[1]) };

    // ldmatrix lane offsets (bytes)
    const uint32_t kOff = (uint32_t)(((grp4 >> 1) * 8 + (lid & 7)) * LDKH
                                     + (grp4 & 1) * 8) * 2;
    // trans-ldmatrix: lane -> memory row (key) = lid&15, col (hd) = (lid>>4)*8
    const uint32_t vOff = (uint32_t)((lid & 15) * LDKH + (lid >> 4) * 8) * 2;

    // ---- Q a-frags straight from global ----------------------------------
    uint32_t qa[2][2][4];
#pragma unroll
    for (int mi = 0; mi < 2; ++mi) {
        const int r0 = wm + mi * 16 + g, r1 = r0 + 8;
        const __half* q0 = base + (size_t)r0 * QKVC + h * HDIM;
        const __half* q1 = base + (size_t)r1 * QKVC + h * HDIM;
#pragma unroll
        for (int ks = 0; ks < 2; ++ks) {
            const int k2 = ks * 16 + 2 * t4;
            qa[mi][ks][0] = (r0 < NTOK) ? *reinterpret_cast<const uint32_t*>(q0 + k2) : 0u;
            qa[mi][ks][1] = (r1 < NTOK) ? *reinterpret_cast<const uint32_t*>(q1 + k2) : 0u;
            qa[mi][ks][2] = (r0 < NTOK) ? *reinterpret_cast<const uint32_t*>(q0 + k2 + 8) : 0u;
            qa[mi][ks][3] = (r1 < NTOK) ? *reinterpret_cast<const uint32_t*>(q1 + k2 + 8) : 0u;
        }
    }

    float o[2][4][4];
#pragma unroll
    for (int mi = 0; mi < 2; ++mi)
#pragma unroll
        for (int n = 0; n < 4; ++n)
#pragma unroll
            for (int q = 0; q < 4; ++q) o[mi][n][q] = 0.f;
    float mrow[2][2] = {{-1e30f, -1e30f}, {-1e30f, -1e30f}};
    float lrow[2][2] = {{0.f, 0.f}, {0.f, 0.f}};

    const __half* bp = biasP + ((size_t)h * NPAD + wm) * KPAD;

    // K and V tiles both [key][hd], cp.async with zero-fill on pad keys
    auto load_kv = [&](int ch, int buf) {
        const int j0 = ch * 64;
#pragma unroll
        for (int i = 0; i < 2; ++i) {
            int f = tid + i * 128;                 // 256 16B slots each
            int row = f >> 2, c16 = (f & 3) * 8;
            int kr = j0 + row;
            uint32_t pred = (kr < NTOK) ? 16u : 0u;
            const __half* rp = base + (size_t)kr * QKVC + h * HDIM + c16;
            CP_ASYNC16P(KsU[buf] + (uint32_t)(row * LDKH + c16) * 2, rp + CDIM, pred);
            CP_ASYNC16P(VsU[buf] + (uint32_t)(row * LDKH + c16) * 2, rp + 2 * CDIM, pred);
        }
    };

    auto compute = [&](auto NIc, auto NGRPc, int ch, int buf) {
        constexpr int NI   = decltype(NIc)::value;
        constexpr int NGRP = decltype(NGRPc)::value;
        const int j0 = ch * 64;
        if (!active) return;

        // ---- S = Q K^T ----------------------------------------------------
        float c[2][8][4];
#pragma unroll
        for (int mi = 0; mi < 2; ++mi)
#pragma unroll
            for (int ni = 0; ni < NI; ++ni)
#pragma unroll
                for (int q = 0; q < 4; ++q) c[mi][ni][q] = 0.f;
#pragma unroll
        for (int ks = 0; ks < 2; ++ks) {
            uint32_t kb[8][2];
#pragma unroll
            for (int p = 0; p < (NI + 1) / 2; ++p)
                ldsm_x4(kb[2*p][0], kb[2*p][1], kb[2*p+1][0], kb[2*p+1][1],
                        KsU[buf] + kOff + (uint32_t)(p * 16 * LDKH * 2 + ks * 32));
#pragma unroll
            for (int mi = 0; mi < 2; ++mi)
#pragma unroll
                for (int ni = 0; ni < NI; ++ni)
                    mma_f16(c[mi][ni], qa[mi][ks], kb[ni]);
        }
        // ---- scale + bias -------------------------------------------------
#pragma unroll
        for (int mi = 0; mi < 2; ++mi) {
            const __half* b0p = bp + (size_t)(mi * 16 + g) * KPAD + j0 + 2 * t4;
            const __half* b1p = bp + (size_t)(mi * 16 + 8 + g) * KPAD + j0 + 2 * t4;
#pragma unroll
            for (int ni = 0; ni < NI; ++ni) {
                float2 bb0 = __half22float2(*reinterpret_cast<const __half2*>(b0p + ni * 8));
                float2 bb1 = __half22float2(*reinterpret_cast<const __half2*>(b1p + ni * 8));
                c[mi][ni][0] = c[mi][ni][0] * scale + bb0.x;
                c[mi][ni][1] = c[mi][ni][1] * scale + bb0.y;
                c[mi][ni][2] = c[mi][ni][2] * scale + bb1.x;
                c[mi][ni][3] = c[mi][ni][3] * scale + bb1.y;
            }
        }
        // ---- online softmax ----------------------------------------------
#pragma unroll
        for (int mi = 0; mi < 2; ++mi) {
            float mx0 = c[mi][0][0], mx1 = c[mi][0][2];
#pragma unroll
            for (int ni = 0; ni < NI; ++ni) {
                mx0 = fmaxf(mx0, fmaxf(c[mi][ni][0], c[mi][ni][1]));
                mx1 = fmaxf(mx1, fmaxf(c[mi][ni][2], c[mi][ni][3]));
            }
            mx0 = fmaxf(mx0, __shfl_xor_sync(0xFFFFFFFF, mx0, 1));
            mx0 = fmaxf(mx0, __shfl_xor_sync(0xFFFFFFFF, mx0, 2));
            mx1 = fmaxf(mx1, __shfl_xor_sync(0xFFFFFFFF, mx1, 1));
            mx1 = fmaxf(mx1, __shfl_xor_sync(0xFFFFFFFF, mx1, 2));
            float nm0 = fmaxf(mrow[mi][0], mx0);
            float nm1 = fmaxf(mrow[mi][1], mx1);
            float cr0 = __expf(mrow[mi][0] - nm0);
            float cr1 = __expf(mrow[mi][1] - nm1);
            mrow[mi][0] = nm0; mrow[mi][1] = nm1;
#pragma unroll
            for (int n = 0; n < 4; ++n) {
                o[mi][n][0] *= cr0; o[mi][n][1] *= cr0;
                o[mi][n][2] *= cr1; o[mi][n][3] *= cr1;
            }
            float s0 = 0.f, s1 = 0.f;
#pragma unroll
            for (int ni = 0; ni < NI; ++ni) {
                c[mi][ni][0] = __expf(c[mi][ni][0] - nm0); s0 += c[mi][ni][0];
                c[mi][ni][1] = __expf(c[mi][ni][1] - nm0); s0 += c[mi][ni][1];
                c[mi][ni][2] = __expf(c[mi][ni][2] - nm1); s1 += c[mi][ni][2];
                c[mi][ni][3] = __expf(c[mi][ni][3] - nm1); s1 += c[mi][ni][3];
            }
            s0 += __shfl_xor_sync(0xFFFFFFFF, s0, 1);
            s0 += __shfl_xor_sync(0xFFFFFFFF, s0, 2);
            s1 += __shfl_xor_sync(0xFFFFFFFF, s1, 1);
            s1 += __shfl_xor_sync(0xFFFFFFFF, s1, 2);
            lrow[mi][0] = lrow[mi][0] * cr0 + s0;
            lrow[mi][1] = lrow[mi][1] * cr1 + s1;
            // zero pad-key tiles consumed by PV groups
#pragma unroll
            for (int ni = NI; ni < 2 * NGRP; ++ni)
#pragma unroll
                for (int q = 0; q < 4; ++q) c[mi][ni][q] = 0.f;
        }
        // ---- O += P V (V b-frags via trans ldmatrix) ----------------------
#pragma unroll
        for (int grp = 0; grp < NGRP; ++grp) {
            uint32_t vb[4][2];
            const uint32_t va = VsU[buf] + vOff + (uint32_t)(grp * 16 * LDKH * 2);
            ldsm_x4_t(vb[0][0], vb[0][1], vb[1][0], vb[1][1], va);
            ldsm_x4_t(vb[2][0], vb[2][1], vb[3][0], vb[3][1], va + 32);
#pragma unroll
            for (int mi = 0; mi < 2; ++mi) {
                uint32_t pa[4];
                pa[0] = pack_h2(c[mi][2 * grp][0],     c[mi][2 * grp][1]);
                pa[1] = pack_h2(c[mi][2 * grp][2],     c[mi][2 * grp][3]);
                pa[2] = pack_h2(c[mi][2 * grp + 1][0], c[mi][2 * grp + 1][1]);
                pa[3] = pack_h2(c[mi][2 * grp + 1][2], c[mi][2 * grp + 1][3]);
#pragma unroll
                for (int n = 0; n < 4; ++n)
                    mma_f16(o[mi][n], pa, vb[n]);
            }
        }
    };

    load_kv(0, 0);
    CP_COMMIT();
    for (int ch = 0; ch < 5; ++ch) {
        const int bu = ch & 1;
        load_kv(ch + 1, bu ^ 1);
        CP_COMMIT();
        CP_WAIT1();
        __syncthreads();
        compute(IC<8>{}, IC<4>{}, ch, bu);
        __syncthreads();
    }
    CP_WAIT0();
    __syncthreads();
    compute(IC<3>{}, IC<2>{}, 5, 1);   // keys 320..343 (+pad)

    if (active) {
#pragma unroll
        for (int mi = 0; mi < 2; ++mi) {
            const float i0 = 1.f / lrow[mi][0];
            const float i1 = 1.f / lrow[mi][1];
            const int r0 = wm + mi * 16 + g;
            const int r1 = r0 + 8;
            if (r0 < NTOK) {
                __half* op = out + ((size_t)b * NTOK + r0) * CDIM + h * HDIM + 2 * t4;
#pragma unroll
                for (int n = 0; n < 4; ++n)
                    *reinterpret_cast<uint32_t*>(op + n * 8) =
                        pack_h2(o[mi][n][0] * i0, o[mi][n][1] * i0);
            }
            if (r1 < NTOK) {
                __half* op = out + ((size_t)b * NTOK + r1) * CDIM + h * HDIM + 2 * t4;
#pragma unroll
                for (int n = 0; n < 4; ++n)
                    *reinterpret_cast<uint32_t*>(op + n * 8) =
                        pack_h2(o[mi][n][2] * i1, o[mi][n][3] * i1);
            }
        }
    }
}

// ---------------- launch ------------------------------------------------------
extern "C" void kernel_launch(void* const* d_in, const int* in_sizes, int n_in,
                              void* d_out, int out_size)
{
    const float* x       = (const float*)d_in[0];
    const float* qkv_w   = (const float*)d_in[1];
    const float* qkv_b   = (const float*)d_in[2];
    const float* proj_w  = (const float*)d_in[3];
    const float* proj_b  = (const float*)d_in[4];
    const float* bt      = (const float*)d_in[5];
    const int*   ridx    = (const int*)d_in[6];
    float*       out     = (float*)d_out;

    void *p_qkv, *p_att, *p_bias, *p_xh, *p_wqt, *p_wpt;
    cudaGetSymbolAddress(&p_qkv,  g_qkv);
    cudaGetSymbolAddress(&p_att,  g_att);
    cudaGetSymbolAddress(&p_bias, g_biasH);
    cudaGetSymbolAddress(&p_xh,   g_xh);
    cudaGetSymbolAddress(&p_wqt,  g_wqt);
    cudaGetSymbolAddress(&p_wpt,  g_wpt);
    __half* qkvh = (__half*)p_qkv;
    __half* atth = (__half*)p_att;
    __half* bias = (__half*)p_bias;
    __half* xh   = (__half*)p_xh;
    __half* wqt  = (__half*)p_wqt;
    __half* wpt  = (__half*)p_wpt;

    cudaFuncSetAttribute(mma_gemm_h<false>,
                         cudaFuncAttributeMaxDynamicSharedMemorySize, GSM_TOT);
    cudaFuncSetAttribute(mma_gemm_h<true>,
                         cudaFuncAttributeMaxDynamicSharedMemorySize, GSM_TOT);

    // 0) fused prep (x->half | weight transposes | bias expand), one launch
    prep_kernel<<<PREP_BLOCKS, 256>>>(x, qkv_w, proj_w, bt, ridx,
                                      xh, wqt, wpt, bias);

    // 1) QKV projection
    mma_gemm_h<false><<<dim3(QKVC / 128, MROWS / 128), 256, GSM_TOT>>>(
        xh, wqt, qkv_b, qkvh, QKVC);

    // 2) fp16 flash attention
    attn_f16_kernel<<<dim3(NHEADS, NWIN, 3), AT_THREADS>>>(qkvh, bias, atth);

    // 3) output projection
    mma_gemm_h<true><<<dim3(CDIM / 128, MROWS / 128), 256, GSM_TOT>>>(
        atth, wpt, proj_b, out, CDIM);
}

// round 11
// speedup vs baseline: 2.7093x; 1.0784x over previous
#include <cuda_runtime.h>
#include <cuda_fp16.h>
#include <cstdint>
#include <cstdio>

#define NTOK   343
#define NWIN   256
#define NHEADS 12
#define HDIM   32
#define CDIM   384
#define MROWS  (NWIN * NTOK)     // 87808
#define QKVC   (3 * CDIM)        // 1152
#define NPAD   384
#define KPAD   384

// ---------------- scratch (static device globals) ---------------------------
// GEMM A/B inputs live in chunk-major pre-swizzled layout: [kchunk][row][64]
// with 16B-group g of row r stored at (g ^ (r&7)).
__device__ __half g_qkv[(size_t)MROWS * QKVC];     // normal layout (attn input)
__device__ __half g_att[(size_t)MROWS * CDIM];     // chunk-major swizzled (proj A)
__device__ __half g_biasH[NHEADS * NPAD * KPAD];
__device__ __half g_xh[(size_t)MROWS * CDIM];      // chunk-major swizzled (qkv A)
__device__ __half g_wqt[(size_t)QKVC * CDIM];      // chunk-major swizzled (qkv B)
__device__ __half g_wpt[(size_t)CDIM * CDIM];      // chunk-major swizzled (proj B)

template<int N> struct IC { static constexpr int value = N; };

// ======================= helpers ============================================
__device__ __forceinline__ uint32_t smem_u32(const void* p) {
    uint32_t a;
    asm("{ .reg .u64 t; cvta.to.shared.u64 t, %1; cvt.u32.u64 %0, t; }" : "=r"(a) : "l"(p));
    return a;
}
__device__ __forceinline__ uint32_t pack_h2(float lo, float hi) {
    uint32_t r;
    asm("cvt.rn.f16x2.f32 %0, %1, %2;" : "=r"(r) : "f"(hi), "f"(lo));
    return r;
}
__device__ __forceinline__ void ldsm_x4(uint32_t& r0, uint32_t& r1, uint32_t& r2,
                                        uint32_t& r3, uint32_t addr) {
    asm volatile("ldmatrix.sync.aligned.m8n8.x4.shared.b16 {%0,%1,%2,%3}, [%4];"
                 : "=r"(r0), "=r"(r1), "=r"(r2), "=r"(r3) : "r"(addr));
}
__device__ __forceinline__ void ldsm_x4_t(uint32_t& r0, uint32_t& r1, uint32_t& r2,
                                          uint32_t& r3, uint32_t addr) {
    asm volatile("ldmatrix.sync.aligned.m8n8.x4.trans.shared.b16 {%0,%1,%2,%3}, [%4];"
                 : "=r"(r0), "=r"(r1), "=r"(r2), "=r"(r3) : "r"(addr));
}
#define CP_ASYNC16P(dst, src, n) \
    asm volatile("cp.async.cg.shared.global [%0], [%1], 16, %2;" :: "r"(dst), "l"(src), "r"(n))
#define CP_COMMIT() asm volatile("cp.async.commit_group;" ::: "memory")
#define CP_WAIT1()  asm volatile("cp.async.wait_group 1;" ::: "memory")
#define CP_WAIT0()  asm volatile("cp.async.wait_group 0;" ::: "memory")

#define MBARRIER_INIT(mb, cnt) \
    asm volatile("mbarrier.init.shared.b64 [%0], %1;" :: "r"((uint32_t)(mb)), "r"((uint32_t)(cnt)) : "memory")
#define MBARRIER_EXPECT_TX(mb, bytes) \
    asm volatile("mbarrier.arrive.expect_tx.shared.b64 _, [%0], %1;" :: "r"((uint32_t)(mb)), "r"((uint32_t)(bytes)) : "memory")
#define CP_BULK(dst, src, bytes, mb) \
    asm volatile("cp.async.bulk.shared::cluster.global.mbarrier::complete_tx::bytes [%0], [%1], %2, [%3];" \
                 :: "r"((uint32_t)(dst)), "l"(src), "r"((uint32_t)(bytes)), "r"((uint32_t)(mb)) : "memory")
#define MBARRIER_WAIT_PARITY(mb, ph) do {                                         \
    uint32_t _mb = (uint32_t)(mb); uint32_t _p = (uint32_t)(ph); uint32_t _done;  \
    asm volatile("{\n\t.reg .pred p;\n\t"                                         \
        "mbarrier.try_wait.parity.acquire.cta.shared::cta.b64 p, [%1], %2;\n\t"   \
        "selp.b32 %0, 1, 0, p;\n\t}" : "=r"(_done) : "r"(_mb), "r"(_p) : "memory"); \
    if (!_done) {                                                                 \
        asm volatile("{\n\t.reg .pred P1;\n\t"                                    \
            "WL_%=:\n\t"                                                          \
            "mbarrier.try_wait.parity.acquire.cta.shared::cta.b64 P1, [%0], %1, 0x989680;\n\t" \
            "@P1 bra.uni WD_%=;\n\t"                                              \
            "bra.uni WL_%=;\n\t"                                                  \
            "WD_%=:\n\t}" :: "r"(_mb), "r"(_p) : "memory");                       \
    }                                                                             \
} while (0)

__device__ __forceinline__ void mma_f16(float* c, const uint32_t* a, const uint32_t* b) {
    asm volatile(
        "mma.sync.aligned.m16n8k16.row.col.f32.f16.f16.f32 "
        "{%0,%1,%2,%3}, {%4,%5,%6,%7}, {%8,%9}, {%0,%1,%2,%3};"
        : "+f"(c[0]), "+f"(c[1]), "+f"(c[2]), "+f"(c[3])
        : "r"(a[0]), "r"(a[1]), "r"(a[2]), "r"(a[3]), "r"(b[0]), "r"(b[1]));
}

// ======================= fused prep kernel ==================================
// x -> half (chunk-major swizzled) | bias expand | both weight transposes
#define NBX  16464   // MROWS*CDIM/8 / 256
#define NBB  6912
#define NBTQ 432
#define NBTP 144
#define PREP_BLOCKS (NBX + NBB + NBTQ + NBTP)

__global__ __launch_bounds__(256) void prep_kernel(
    const float* __restrict__ x, const float* __restrict__ qkv_w,
    const float* __restrict__ proj_w, const float* __restrict__ bt,
    const int* __restrict__ ridx,
    __half* __restrict__ xh, __half* __restrict__ wqt,
    __half* __restrict__ wpt, __half* __restrict__ bf)
{
    __shared__ float t[32][33];
    const int bid = blockIdx.x;
    const int tid = threadIdx.x;

    if (bid < NBX) {
        // 8 floats -> one swizzled 16B group
        size_t e = ((size_t)bid * 256 + tid) * 8;
        int row = (int)(e / CDIM);
        int hcf = (int)(e % CDIM);
        int c   = hcf >> 6;
        int grp = (hcf & 63) >> 3;
        float4 v0 = *reinterpret_cast<const float4*>(x + e);
        float4 v1 = *reinterpret_cast<const float4*>(x + e + 4);
        uint4 o;
        o.x = pack_h2(v0.x, v0.y); o.y = pack_h2(v0.z, v0.w);
        o.z = pack_h2(v1.x, v1.y); o.w = pack_h2(v1.z, v1.w);
        size_t dst = ((size_t)c * MROWS + row) * 64 + ((grp ^ (row & 7)) << 3);
        *reinterpret_cast<uint4*>(xh + dst) = o;
        return;
    }
    if (bid < NBX + NBB) {
        int idx = (bid - NBX) * 256 + tid;
        int h   = idx / (NPAD * KPAD);
        int rem = idx - h * NPAD * KPAD;
        int r   = rem / KPAD;
        int k   = rem - r * KPAD;
        float v;
        if (k >= NTOK)      v = -60000.f;
        else if (r >= NTOK) v = 0.f;
        else                v = bt[ridx[r * NTOK + k] * NHEADS + h];
        bf[idx] = __float2half(v);
        return;
    }
    // weight transposes: W[k][Nw] -> chunk-major swizzled [k/64][n][64]
    const int tx = tid & 31, ty = tid >> 5;
    const float* W; __half* Wt; int Nw, bx, by;
    if (bid < NBX + NBB + NBTQ) {
        int bb = bid - NBX - NBB;
        W = qkv_w; Wt = wqt; Nw = QKVC;
        bx = bb % (QKVC / 32); by = bb / (QKVC / 32);
    } else {
        int bb = bid - NBX - NBB - NBTQ;
        W = proj_w; Wt = wpt; Nw = CDIM;
        bx = bb % (CDIM / 32); by = bb / (CDIM / 32);
    }
    int n0 = bx * 32, k0 = by * 32;
#pragma unroll
    for (int s = 0; s < 4; ++s) {
        int k = k0 + ty + s * 8;
        t[ty + s * 8][tx] = W[(size_t)k * Nw + n0 + tx];
    }
    __syncthreads();
#pragma unroll
    for (int s = 0; s < 4; ++s) {
        int n = n0 + ty + s * 8;
        int k = k0 + tx;
        int c = k >> 6, hc = k & 63;
        size_t dst = ((size_t)c * Nw + n) * 64
                     + ((((hc >> 3) ^ (n & 7))) << 3) + (hc & 7);
        Wt[dst] = __float2half(t[tx][ty + s * 8]);
    }
}

// ======================= fp16 mma GEMM (bulk-copy pipeline) =================
// A: [c][MROWS][64] swizzled; B: [c][Ntot][64] swizzled. CTA 128x128, BK=64.
#define GNCHUNK  6
#define GSTAGE_H 8192                     // halves per operand stage (16KB)
#define GSM_TOT  (4 * GSTAGE_H * 2 + 16)  // 2 stages x (A+B) + 2 mbarriers

template<bool OUT_FLOAT>
__global__ __launch_bounds__(256, 2) void mma_gemm_h(
    const __half* __restrict__ A, const __half* __restrict__ Wt,
    const float* __restrict__ bias, void* __restrict__ Cout, int Ntot)
{
    extern __shared__ __half smh[];
    const uint32_t sbase = smem_u32(smh);
    const uint32_t sAu[2] = { sbase,                  sbase + 2 * GSTAGE_H * 2 };
    const uint32_t sBu[2] = { sbase + GSTAGE_H * 2,   sbase + 3 * GSTAGE_H * 2 };
    const uint32_t mb[2]  = { sbase + 4 * GSTAGE_H * 2, sbase + 4 * GSTAGE_H * 2 + 8 };

    const int tid = threadIdx.x;
    const int wid = tid >> 5, lid = tid & 31;
    const int g = lid >> 2, t4 = lid & 3;
    const int grp4 = lid >> 3;
    const int x7 = lid & 7;
    const int wm = (wid & 1) * 64;
    const int wn = (wid >> 1) * 32;
    const int bm = blockIdx.y * 128;
    const int bn = blockIdx.x * 128;

    const uint32_t aRow = (uint32_t)(wm + (grp4 & 1) * 8 + x7) * 128;
    const int cA = grp4 >> 1;
    const uint32_t bRow = (uint32_t)(wn + (grp4 >> 1) * 8 + x7) * 128;
    const int cB = grp4 & 1;

    if (tid == 0) { MBARRIER_INIT(mb[0], 1); MBARRIER_INIT(mb[1], 1); }
    __syncthreads();
    int ph[2] = {0, 0};

    float acc[4][4][4];
#pragma unroll
    for (int i = 0; i < 4; ++i)
#pragma unroll
        for (int j = 0; j < 4; ++j)
#pragma unroll
            for (int q = 0; q < 4; ++q) acc[i][j][q] = 0.f;

    auto issue = [&](int c, int buf) {
        if (tid == 0) {
            MBARRIER_EXPECT_TX(mb[buf], 32768u);
            CP_BULK(sAu[buf], A  + ((size_t)c * MROWS + bm) * 64, 16384u, mb[buf]);
            CP_BULK(sBu[buf], Wt + ((size_t)c * Ntot  + bn) * 64, 16384u, mb[buf]);
        }
    };

    issue(0, 0);
    for (int c = 0; c < GNCHUNK; ++c) {
        const int buf = c & 1;
        if (c + 1 < GNCHUNK) issue(c + 1, buf ^ 1);
        MBARRIER_WAIT_PARITY(mb[buf], ph[buf]);
        ph[buf] ^= 1;

#pragma unroll
        for (int ks = 0; ks < 4; ++ks) {
            uint32_t af[4][4], bf[4][2];
            const uint32_t aSw = (uint32_t)(((ks * 2 + cA) ^ x7) << 4);
            const uint32_t bSw = (uint32_t)(((ks * 2 + cB) ^ x7) << 4);
#pragma unroll
            for (int mi = 0; mi < 4; ++mi)
                ldsm_x4(af[mi][0], af[mi][1], af[mi][2], af[mi][3],
                        sAu[buf] + aRow + (uint32_t)(mi * 2048) + aSw);
            ldsm_x4(bf[0][0], bf[0][1], bf[1][0], bf[1][1], sBu[buf] + bRow + bSw);
            ldsm_x4(bf[2][0], bf[2][1], bf[3][0], bf[3][1], sBu[buf] + bRow + 2048 + bSw);
#pragma unroll
            for (int mi = 0; mi < 4; ++mi)
#pragma unroll
                for (int ni = 0; ni < 4; ++ni)
                    mma_f16(acc[mi][ni], af[mi], bf[ni]);
        }
        __syncthreads();   // all warps done with buf before it is re-filled
    }

#pragma unroll
    for (int mi = 0; mi < 4; ++mi) {
#pragma unroll
        for (int ni = 0; ni < 4; ++ni) {
            const int row = bm + wm + mi * 16 + g;
            const int col = bn + wn + ni * 8 + t4 * 2;
            const float b0 = __ldg(&bias[col]), b1 = __ldg(&bias[col + 1]);
            float v00 = acc[mi][ni][0] + b0, v01 = acc[mi][ni][1] + b1;
            float v10 = acc[mi][ni][2] + b0, v11 = acc[mi][ni][3] + b1;
            if (OUT_FLOAT) {
                float* C = reinterpret_cast<float*>(Cout);
                *reinterpret_cast<float2*>(&C[(size_t)row * Ntot + col])       = make_float2(v00, v01);
                *reinterpret_cast<float2*>(&C[(size_t)(row + 8) * Ntot + col]) = make_float2(v10, v11);
            } else {
                __half* C = reinterpret_cast<__half*>(Cout);
                *reinterpret_cast<uint32_t*>(&C[(size_t)row * Ntot + col])       = pack_h2(v00, v01);
                *reinterpret_cast<uint32_t*>(&C[(size_t)(row + 8) * Ntot + col]) = pack_h2(v10, v11);
            }
        }
    }
}

// ======================= fp16 flash attention ===============================
// unchanged compute; epilogue writes chunk-major swizzled att (proj A input)
#define AT_THREADS 128
#define LDKH 40

__global__ __launch_bounds__(AT_THREADS, 1) void attn_f16_kernel(
    const __half* __restrict__ qkv, const __half* __restrict__ biasP,
    __half* __restrict__ out)
{
    __shared__ __half Ks[2][64 * LDKH];
    __shared__ __half Vs[2][64 * LDKH];
    const int h   = blockIdx.x;
    const int b   = blockIdx.y;
    const int tid = threadIdx.x;
    const int wid = tid >> 5, lid = tid & 31;
    const int g = lid >> 2, t4 = lid & 3;
    const int grp4 = lid >> 3;
    const int wm = blockIdx.z * 128 + wid * 32;
    const bool active = wm < NTOK;
    const __half* base = qkv + (size_t)b * NTOK * QKVC;
    const float scale = 0.17677669529663687f;
    const uint32_t KsU[2] = { smem_u32(Ks[0]), smem_u32(Ks[1]) };
    const uint32_t VsU[2] = { smem_u32(Vs[0]), smem_u32(Vs[1]) };

    const uint32_t kOff = (uint32_t)(((grp4 >> 1) * 8 + (lid & 7)) * LDKH
                                     + (grp4 & 1) * 8) * 2;
    const uint32_t vOff = (uint32_t)((lid & 15) * LDKH + (lid >> 4) * 8) * 2;

    uint32_t qa[2][2][4];
#pragma unroll
    for (int mi = 0; mi < 2; ++mi) {
        const int r0 = wm + mi * 16 + g, r1 = r0 + 8;
        const __half* q0 = base + (size_t)r0 * QKVC + h * HDIM;
        const __half* q1 = base + (size_t)r1 * QKVC + h * HDIM;
#pragma unroll
        for (int ks = 0; ks < 2; ++ks) {
            const int k2 = ks * 16 + 2 * t4;
            qa[mi][ks][0] = (r0 < NTOK) ? *reinterpret_cast<const uint32_t*>(q0 + k2) : 0u;
            qa[mi][ks][1] = (r1 < NTOK) ? *reinterpret_cast<const uint32_t*>(q1 + k2) : 0u;
            qa[mi][ks][2] = (r0 < NTOK) ? *reinterpret_cast<const uint32_t*>(q0 + k2 + 8) : 0u;
            qa[mi][ks][3] = (r1 < NTOK) ? *reinterpret_cast<const uint32_t*>(q1 + k2 + 8) : 0u;
        }
    }

    float o[2][4][4];
#pragma unroll
    for (int mi = 0; mi < 2; ++mi)
#pragma unroll
        for (int n = 0; n < 4; ++n)
#pragma unroll
            for (int q = 0; q < 4; ++q) o[mi][n][q] = 0.f;
    float mrow[2][2] = {{-1e30f, -1e30f}, {-1e30f, -1e30f}};
    float lrow[2][2] = {{0.f, 0.f}, {0.f, 0.f}};

    const __half* bp = biasP + ((size_t)h * NPAD + wm) * KPAD;

    auto load_kv = [&](int ch, int buf) {
        const int j0 = ch * 64;
#pragma unroll
        for (int i = 0; i < 2; ++i) {
            int f = tid + i * 128;
            int row = f >> 2, c16 = (f & 3) * 8;
            int kr = j0 + row;
            uint32_t pred = (kr < NTOK) ? 16u : 0u;
            const __half* rp = base + (size_t)kr * QKVC + h * HDIM + c16;
            CP_ASYNC16P(KsU[buf] + (uint32_t)(row * LDKH + c16) * 2, rp + CDIM, pred);
            CP_ASYNC16P(VsU[buf] + (uint32_t)(row * LDKH + c16) * 2, rp + 2 * CDIM, pred);
        }
    };

    auto compute = [&](auto NIc, auto NGRPc, int ch, int buf) {
        constexpr int NI   = decltype(NIc)::value;
        constexpr int NGRP = decltype(NGRPc)::value;
        const int j0 = ch * 64;
        if (!active) return;

        float c[2][8][4];
#pragma unroll
        for (int mi = 0; mi < 2; ++mi)
#pragma unroll
            for (int ni = 0; ni < NI; ++ni)
#pragma unroll
                for (int q = 0; q < 4; ++q) c[mi][ni][q] = 0.f;
#pragma unroll
        for (int ks = 0; ks < 2; ++ks) {
            uint32_t kb[8][2];
#pragma unroll
            for (int p = 0; p < (NI + 1) / 2; ++p)
                ldsm_x4(kb[2*p][0], kb[2*p][1], kb[2*p+1][0], kb[2*p+1][1],
                        KsU[buf] + kOff + (uint32_t)(p * 16 * LDKH * 2 + ks * 32));
#pragma unroll
            for (int mi = 0; mi < 2; ++mi)
#pragma unroll
                for (int ni = 0; ni < NI; ++ni)
                    mma_f16(c[mi][ni], qa[mi][ks], kb[ni]);
        }
#pragma unroll
        for (int mi = 0; mi < 2; ++mi) {
            const __half* b0p = bp + (size_t)(mi * 16 + g) * KPAD + j0 + 2 * t4;
            const __half* b1p = bp + (size_t)(mi * 16 + 8 + g) * KPAD + j0 + 2 * t4;
#pragma unroll
            for (int ni = 0; ni < NI; ++ni) {
                float2 bb0 = __half22float2(*reinterpret_cast<const __half2*>(b0p + ni * 8));
                float2 bb1 = __half22float2(*reinterpret_cast<const __half2*>(b1p + ni * 8));
                c[mi][ni][0] = c[mi][ni][0] * scale + bb0.x;
                c[mi][ni][1] = c[mi][ni][1] * scale + bb0.y;
                c[mi][ni][2] = c[mi][ni][2] * scale + bb1.x;
                c[mi][ni][3] = c[mi][ni][3] * scale + bb1.y;
            }
        }
#pragma unroll
        for (int mi = 0; mi < 2; ++mi) {
            float mx0 = c[mi][0][0], mx1 = c[mi][0][2];
#pragma unroll
            for (int ni = 0; ni < NI; ++ni) {
                mx0 = fmaxf(mx0, fmaxf(c[mi][ni][0], c[mi][ni][1]));
                mx1 = fmaxf(mx1, fmaxf(c[mi][ni][2], c[mi][ni][3]));
            }
            mx0 = fmaxf(mx0, __shfl_xor_sync(0xFFFFFFFF, mx0, 1));
            mx0 = fmaxf(mx0, __shfl_xor_sync(0xFFFFFFFF, mx0, 2));
            mx1 = fmaxf(mx1, __shfl_xor_sync(0xFFFFFFFF, mx1, 1));
            mx1 = fmaxf(mx1, __shfl_xor_sync(0xFFFFFFFF, mx1, 2));
            float nm0 = fmaxf(mrow[mi][0], mx0);
            float nm1 = fmaxf(mrow[mi][1], mx1);
            float cr0 = __expf(mrow[mi][0] - nm0);
            float cr1 = __expf(mrow[mi][1] - nm1);
            mrow[mi][0] = nm0; mrow[mi][1] = nm1;
#pragma unroll
            for (int n = 0; n < 4; ++n) {
                o[mi][n][0] *= cr0; o[mi][n][1] *= cr0;
                o[mi][n][2] *= cr1; o[mi][n][3] *= cr1;
            }
            float s0 = 0.f, s1 = 0.f;
#pragma unroll
            for (int ni = 0; ni < NI; ++ni) {
                c[mi][ni][0] = __expf(c[mi][ni][0] - nm0); s0 += c[mi][ni][0];
                c[mi][ni][1] = __expf(c[mi][ni][1] - nm0); s0 += c[mi][ni][1];
                c[mi][ni][2] = __expf(c[mi][ni][2] - nm1); s1 += c[mi][ni][2];
                c[mi][ni][3] = __expf(c[mi][ni][3] - nm1); s1 += c[mi][ni][3];
            }
            s0 += __shfl_xor_sync(0xFFFFFFFF, s0, 1);
            s0 += __shfl_xor_sync(0xFFFFFFFF, s0, 2);
            s1 += __shfl_xor_sync(0xFFFFFFFF, s1, 1);
            s1 += __shfl_xor_sync(0xFFFFFFFF, s1, 2);
            lrow[mi][0] = lrow[mi][0] * cr0 + s0;
            lrow[mi][1] = lrow[mi][1] * cr1 + s1;
#pragma unroll
            for (int ni = NI; ni < 2 * NGRP; ++ni)
#pragma unroll
                for (int q = 0; q < 4; ++q) c[mi][ni][q] = 0.f;
        }
#pragma unroll
        for (int grp = 0; grp < NGRP; ++grp) {
            uint32_t vb[4][2];
            const uint32_t va = VsU[buf] + vOff + (uint32_t)(grp * 16 * LDKH * 2);
            ldsm_x4_t(vb[0][0], vb[0][1], vb[1][0], vb[1][1], va);
            ldsm_x4_t(vb[2][0], vb[2][1], vb[3][0], vb[3][1], va + 32);
#pragma unroll
            for (int mi = 0; mi < 2; ++mi) {
                uint32_t pa[4];
                pa[0] = pack_h2(c[mi][2 * grp][0],     c[mi][2 * grp][1]);
                pa[1] = pack_h2(c[mi][2 * grp][2],     c[mi][2 * grp][3]);
                pa[2] = pack_h2(c[mi][2 * grp + 1][0], c[mi][2 * grp + 1][1]);
                pa[3] = pack_h2(c[mi][2 * grp + 1][2], c[mi][2 * grp + 1][3]);
#pragma unroll
                for (int n = 0; n < 4; ++n)
                    mma_f16(o[mi][n], pa, vb[n]);
            }
        }
    };

    load_kv(0, 0);
    CP_COMMIT();
    for (int ch = 0; ch < 5; ++ch) {
        const int bu = ch & 1;
        load_kv(ch + 1, bu ^ 1);
        CP_COMMIT();
        CP_WAIT1();
        __syncthreads();
        compute(IC<8>{}, IC<4>{}, ch, bu);
        __syncthreads();
    }
    CP_WAIT0();
    __syncthreads();
    compute(IC<3>{}, IC<2>{}, 5, 1);

    // epilogue: write chunk-major swizzled att: chunk=h>>1, grp=(h&1)*4+n
    if (active) {
        const int chk = h >> 1;
        const int gbase = (h & 1) * 4;
#pragma unroll
        for (int mi = 0; mi < 2; ++mi) {
            const float i0 = 1.f / lrow[mi][0];
            const float i1 = 1.f / lrow[mi][1];
            const int r0 = wm + mi * 16 + g;
            const int r1 = r0 + 8;
            if (r0 < NTOK) {
                size_t rg = (size_t)b * NTOK + r0;
                __half* op = out + ((size_t)chk * MROWS + rg) * 64 + 2 * t4;
                const int rx = (int)(rg & 7);
#pragma unroll
                for (int n = 0; n < 4; ++n)
                    *reinterpret_cast<uint32_t*>(op + (((gbase + n) ^ rx) << 3)) =
                        pack_h2(o[mi][n][0] * i0, o[mi][n][1] * i0);
            }
            if (r1 < NTOK) {
                size_t rg = (size_t)b * NTOK + r1;
                __half* op = out + ((size_t)chk * MROWS + rg) * 64 + 2 * t4;
                const int rx = (int)(rg & 7);
#pragma unroll
                for (int n = 0; n < 4; ++n)
                    *reinterpret_cast<uint32_t*>(op + (((gbase + n) ^ rx) << 3)) =
                        pack_h2(o[mi][n][2] * i1, o[mi][n][3] * i1);
            }
        }
    }
}

// ---------------- launch ------------------------------------------------------
extern "C" void kernel_launch(void* const* d_in, const int* in_sizes, int n_in,
                              void* d_out, int out_size)
{
    const float* x       = (const float*)d_in[0];
    const float* qkv_w   = (const float*)d_in[1];
    const float* qkv_b   = (const float*)d_in[2];
    const float* proj_w  = (const float*)d_in[3];
    const float* proj_b  = (const float*)d_in[4];
    const float* bt      = (const float*)d_in[5];
    const int*   ridx    = (const int*)d_in[6];
    float*       out     = (float*)d_out;

    void *p_qkv, *p_att, *p_bias, *p_xh, *p_wqt, *p_wpt;
    cudaGetSymbolAddress(&p_qkv,  g_qkv);
    cudaGetSymbolAddress(&p_att,  g_att);
    cudaGetSymbolAddress(&p_bias, g_biasH);
    cudaGetSymbolAddress(&p_xh,   g_xh);
    cudaGetSymbolAddress(&p_wqt,  g_wqt);
    cudaGetSymbolAddress(&p_wpt,  g_wpt);
    __half* qkvh = (__half*)p_qkv;
    __half* atth = (__half*)p_att;
    __half* bias = (__half*)p_bias;
    __half* xh   = (__half*)p_xh;
    __half* wqt  = (__half*)p_wqt;
    __half* wpt  = (__half*)p_wpt;

    cudaFuncSetAttribute(mma_gemm_h<false>,
                         cudaFuncAttributeMaxDynamicSharedMemorySize, GSM_TOT);
    cudaFuncSetAttribute(mma_gemm_h<true>,
                         cudaFuncAttributeMaxDynamicSharedMemorySize, GSM_TOT);

    // 0) fused prep
    prep_kernel<<<PREP_BLOCKS, 256>>>(x, qkv_w, proj_w, bt, ridx,
                                      xh, wqt, wpt, bias);

    // 1) QKV projection (bulk-copy pipeline)
    mma_gemm_h<false><<<dim3(QKVC / 128, MROWS / 128), 256, GSM_TOT>>>(
        xh, wqt, qkv_b, qkvh, QKVC);

    // 2) fp16 flash attention
    attn_f16_kernel<<<dim3(NHEADS, NWIN, 3), AT_THREADS>>>(qkvh, bias, atth);

    // 3) output projection (bulk-copy pipeline)
    mma_gemm_h<true><<<dim3(CDIM / 128, MROWS / 128), 256, GSM_TOT>>>(
        atth, wpt, proj_b, out, CDIM);
}